// round 13
// baseline (speedup 1.0000x reference)
#include <cuda_runtime.h>
#include <cuda_fp16.h>
#include <math_constants.h>
#include <cstdint>

#define EPS 1e-5f

// ---------------- scratch ----------------
__device__ float g_x1[8 * 128 * 4096];
__device__ float g_y2[8 * 128 * 4096];
__device__ float g_attn[8 * 128 * 4096];
__device__ __half g_x2t_hi[8 * 1024 * 128];  // [b][j][c] = X2[c][j]
__device__ __half g_x2t_lo[8 * 1024 * 128];
__device__ __half g_x3t[8 * 128 * 1024];     // [b][c][j] = X3[j][c] = pooledflat[j*128+c] (single fp16)
__device__ __half g_at[8 * 4096 * 256];      // transposed conv input [b][p][c] (single fp16)

// ---------------- helpers ----------------
__device__ __forceinline__ void mma_f16(float& c0, float& c1, float& c2, float& c3,
                                        uint32_t a0, uint32_t a1, uint32_t a2, uint32_t a3,
                                        uint32_t b0, uint32_t b1)
{
    asm volatile("mma.sync.aligned.m16n8k16.row.col.f32.f16.f16.f32 "
                 "{%0,%1,%2,%3}, {%4,%5,%6,%7}, {%8,%9}, {%0,%1,%2,%3};"
                 : "+f"(c0), "+f"(c1), "+f"(c2), "+f"(c3)
                 : "r"(a0), "r"(a1), "r"(a2), "r"(a3), "r"(b0), "r"(b1));
}
// pack (e0 -> low, e1 -> high) as f16x2; also residual pack
__device__ __forceinline__ void split2h(float e0, float e1, uint32_t& hi, uint32_t& lo)
{
    asm("cvt.rn.f16x2.f32 %0, %1, %2;" : "=r"(hi) : "f"(e1), "f"(e0));
    __half2 hp = *reinterpret_cast<__half2*>(&hi);
    float f0h = __half2float(hp.x);   // low  = e0
    float f1h = __half2float(hp.y);   // high = e1
    asm("cvt.rn.f16x2.f32 %0, %1, %2;" : "=r"(lo) : "f"(e1 - f1h), "f"(e0 - f0h));
}
__device__ __forceinline__ uint32_t smem_u32(const void* p) {
    uint32_t a;
    asm("{ .reg .u64 t; cvta.to.shared.u64 t, %1; cvt.u32.u64 %0, t; }" : "=r"(a) : "l"(p));
    return a;
}
#define CP_ASYNC16(dst, src) asm volatile("cp.async.cg.shared.global [%0], [%1], 16;" :: "r"(dst), "l"(src))
#define CP_COMMIT()          asm volatile("cp.async.commit_group;" ::: "memory")
#define CP_WAIT1()           asm volatile("cp.async.wait_group 1;" ::: "memory")

// ---------------- fused maxpool + both attention operand layouts ----------------
__global__ __launch_bounds__(256) void pool_split_kernel(
    const float* __restrict__ y2,
    __half* __restrict__ x2h, __half* __restrict__ x2l, __half* __restrict__ x3)
{
    __shared__ float t[32][33];
    const int p  = blockIdx.x;
    const int c0 = blockIdx.y * 32;
    const int b  = blockIdx.z;
    const int tid = threadIdx.x;
    const int q   = tid & 31;
    const int ccb = tid >> 5;

    const float* src = y2 + (size_t)b * 128 * 4096;
    const int r0 = 2 * p - 1;
#pragma unroll
    for (int k = 0; k < 4; k++) {
        int cc = ccb + 8 * k;
        const float* row = src + (size_t)(c0 + cc) * 4096;
        float m = -CUDART_INF_F;
#pragma unroll
        for (int dr = 0; dr < 3; dr++) {
            int r = r0 + dr;
            if (r < 0 || r >= 64) continue;
#pragma unroll
            for (int dc = 0; dc < 3; dc++) {
                int col = 2 * q - 1 + dc;
                if (col < 0 || col >= 64) continue;
                m = fmaxf(m, row[r * 64 + col]);
            }
        }
        t[cc][q] = m;
    }
    __syncthreads();

    const int cc2 = tid & 31;
#pragma unroll
    for (int k = 0; k < 4; k++) {
        int q2 = ccb + 8 * k;
        float v = t[cc2][q2];
        __half h = __float2half_rn(v);
        __half l = __float2half_rn(v - __half2float(h));
        size_t o2 = (size_t)b * 131072 + (size_t)(p * 32 + q2) * 128 + c0 + cc2;
        x2h[o2] = h; x2l[o2] = l;
        // x3t[c3][j3] raw-reshape view, single fp16
        int c3 = 32 * (p & 3) + q2;
        int j3 = (c0 + cc2) * 8 + (p >> 2);
        x3[(size_t)b * 131072 + (size_t)c3 * 1024 + j3] = h;
    }
}

// ---------------- transpose + fp16: NCHW [b][C][P] -> [b][p][c] single fp16 ----------------
__global__ void transpose_split_kernel(const float* __restrict__ src_,
                                       __half* __restrict__ oh, int C, int P)
{
    __shared__ float t[32][33];
    int b = blockIdx.z;
    int p0 = blockIdx.x * 32, c0 = blockIdx.y * 32;
    int tx = threadIdx.x, ty = threadIdx.y;
    const float* src = src_ + (size_t)b * C * P;
#pragma unroll
    for (int k = 0; k < 4; k++)
        t[ty + 8 * k][tx] = src[(size_t)(c0 + ty + 8 * k) * P + p0 + tx];
    __syncthreads();
#pragma unroll
    for (int k = 0; k < 4; k++)
        oh[(size_t)b * C * P + (size_t)(p0 + ty + 8 * k) * C + c0 + tx] =
            __float2half_rn(t[tx][ty + 8 * k]);
}

#define CPITCH 72
#define CTILE (128 * CPITCH)

// ---------------- conv1+conv2 merged (W split fp16, B single fp16, 4 mma/frag) ----------------
#define C12_SMEM (6 * CTILE * 2)   // W1h,W1l,W2h,W2l + 2 stages x B = 110592 B

__global__ __launch_bounds__(256) void conv12_mma_kernel(
    const __half* __restrict__ xt,
    const float* __restrict__ W1, const float* __restrict__ bias1,
    const float* __restrict__ gam1, const float* __restrict__ beta1,
    const float* __restrict__ mean1, const float* __restrict__ var1,
    float* __restrict__ Y1,
    const float* __restrict__ W2, const float* __restrict__ bias2,
    const float* __restrict__ gam2, const float* __restrict__ beta2,
    const float* __restrict__ mean2, const float* __restrict__ var2,
    float* __restrict__ Y2)
{
    extern __shared__ __half cs[];
    __half* W1h = cs;
    __half* W1l = cs + CTILE;
    __half* W2h = cs + 2 * CTILE;
    __half* W2l = cs + 3 * CTILE;
    __half* Bbuf[2] = { cs + 4 * CTILE, cs + 5 * CTILE };

    const int HW = 4096;
    const int K  = 256;
    const int b  = blockIdx.z;
    const int p0 = blockIdx.x * 128;
    const int tid  = threadIdx.x;
    const int w    = tid >> 5;
    const int lane = tid & 31;
    const int grp  = lane >> 2;
    const int tig  = lane & 3;

    const __half* srcB = xt + (size_t)b * HW * K + (size_t)p0 * K;

    auto stage_B = [&](int kc, int bi) {
        uint32_t d = smem_u32(Bbuf[bi]);
        int k0 = kc * 64;
#pragma unroll
        for (int l = 0; l < 4; l++) {
            int n = tid + l * 256;
            int r = n >> 3, q = n & 7;
            CP_ASYNC16(d + (uint32_t)(r * (CPITCH * 2) + q * 16), srcB + (size_t)r * K + k0 + q * 8);
        }
    };

    float c1[16][4], c2[16][4];
#pragma unroll
    for (int nt = 0; nt < 16; nt++)
#pragma unroll
        for (int q = 0; q < 4; q++) { c1[nt][q] = 0.f; c2[nt][q] = 0.f; }

    stage_B(0, 0);
    CP_COMMIT();

    for (int kc = 0; kc < 4; kc++) {
        const int k0 = kc * 64;
        __syncthreads();
        if (kc + 1 < 4) stage_B(kc + 1, (kc + 1) & 1);
        CP_COMMIT();
#pragma unroll
        for (int l = 0; l < 16; l++) {
            int n = tid + l * 256;
            int o = n >> 5, kk = n & 31;
            float2 e1 = *(const float2*)(W1 + (size_t)o * K + k0 + 2 * kk);
            float2 e2 = *(const float2*)(W2 + (size_t)o * K + k0 + 2 * kk);
            uint32_t h, lo;
            split2h(e1.x, e1.y, h, lo);
            *(uint32_t*)(W1h + o * CPITCH + 2 * kk) = h;
            *(uint32_t*)(W1l + o * CPITCH + 2 * kk) = lo;
            split2h(e2.x, e2.y, h, lo);
            *(uint32_t*)(W2h + o * CPITCH + 2 * kk) = h;
            *(uint32_t*)(W2l + o * CPITCH + 2 * kk) = lo;
        }
        CP_WAIT1();
        __syncthreads();

        const __half* B = Bbuf[kc & 1];
#pragma unroll
        for (int kt = 0; kt < 4; kt++) {
            const int wo = (w * 16 + grp) * CPITCH + kt * 16 + 2 * tig;
            uint32_t a1h0 = *(const uint32_t*)(W1h + wo);
            uint32_t a1h1 = *(const uint32_t*)(W1h + wo + 8 * CPITCH);
            uint32_t a1h2 = *(const uint32_t*)(W1h + wo + 8);
            uint32_t a1h3 = *(const uint32_t*)(W1h + wo + 8 * CPITCH + 8);
            uint32_t a1l0 = *(const uint32_t*)(W1l + wo);
            uint32_t a1l1 = *(const uint32_t*)(W1l + wo + 8 * CPITCH);
            uint32_t a1l2 = *(const uint32_t*)(W1l + wo + 8);
            uint32_t a1l3 = *(const uint32_t*)(W1l + wo + 8 * CPITCH + 8);
            uint32_t a2h0 = *(const uint32_t*)(W2h + wo);
            uint32_t a2h1 = *(const uint32_t*)(W2h + wo + 8 * CPITCH);
            uint32_t a2h2 = *(const uint32_t*)(W2h + wo + 8);
            uint32_t a2h3 = *(const uint32_t*)(W2h + wo + 8 * CPITCH + 8);
            uint32_t a2l0 = *(const uint32_t*)(W2l + wo);
            uint32_t a2l1 = *(const uint32_t*)(W2l + wo + 8 * CPITCH);
            uint32_t a2l2 = *(const uint32_t*)(W2l + wo + 8);
            uint32_t a2l3 = *(const uint32_t*)(W2l + wo + 8 * CPITCH + 8);
#pragma unroll
            for (int nt = 0; nt < 16; nt++) {
                const __half* bp = B + (nt * 8 + grp) * CPITCH + kt * 16 + 2 * tig;
                uint32_t bh0 = *(const uint32_t*)bp;
                uint32_t bh1 = *(const uint32_t*)(bp + 8);
                mma_f16(c1[nt][0], c1[nt][1], c1[nt][2], c1[nt][3], a1h0, a1h1, a1h2, a1h3, bh0, bh1);
                mma_f16(c1[nt][0], c1[nt][1], c1[nt][2], c1[nt][3], a1l0, a1l1, a1l2, a1l3, bh0, bh1);
                mma_f16(c2[nt][0], c2[nt][1], c2[nt][2], c2[nt][3], a2h0, a2h1, a2h2, a2h3, bh0, bh1);
                mma_f16(c2[nt][0], c2[nt][1], c2[nt][2], c2[nt][3], a2l0, a2l1, a2l2, a2l3, bh0, bh1);
            }
        }
    }

    const int o_r0 = w * 16 + grp;
    const int o_r1 = o_r0 + 8;
#pragma unroll
    for (int sel = 0; sel < 2; sel++) {
        const float* bias = sel ? bias2 : bias1;
        const float* gam  = sel ? gam2 : gam1;
        const float* beta = sel ? beta2 : beta1;
        const float* mean = sel ? mean2 : mean1;
        const float* var  = sel ? var2 : var1;
        float* Y          = sel ? Y2 : Y1;
        float (*cc)[4]    = sel ? c2 : c1;
        float s0  = gam[o_r0] * rsqrtf(var[o_r0] + EPS);
        float sh0 = beta[o_r0] - mean[o_r0] * s0;
        float bi0 = bias[o_r0];
        float s1  = gam[o_r1] * rsqrtf(var[o_r1] + EPS);
        float sh1 = beta[o_r1] - mean[o_r1] * s1;
        float bi1 = bias[o_r1];
        float* y0 = Y + (size_t)b * 128 * HW + (size_t)o_r0 * HW + p0;
        float* y1 = Y + (size_t)b * 128 * HW + (size_t)o_r1 * HW + p0;
#pragma unroll
        for (int nt = 0; nt < 16; nt++) {
            int p = nt * 8 + 2 * tig;
            *(float2*)(y0 + p) = make_float2(
                fmaxf((cc[nt][0] + bi0) * s0 + sh0, 0.f),
                fmaxf((cc[nt][1] + bi0) * s0 + sh0, 0.f));
            *(float2*)(y1 + p) = make_float2(
                fmaxf((cc[nt][2] + bi1) * s1 + sh1, 0.f),
                fmaxf((cc[nt][3] + bi1) * s1 + sh1, 0.f));
        }
    }
}

// ---------------- conv3 (W split fp16, B single fp16, 2 mma/frag) ----------------
#define CONV_SMEM (4 * CTILE * 2)

__global__ __launch_bounds__(256) void conv_mma_kernel(
    const __half* __restrict__ xt,
    const float* __restrict__ W, const float* __restrict__ bias,
    const float* __restrict__ gam, const float* __restrict__ beta,
    const float* __restrict__ mean, const float* __restrict__ var,
    float* __restrict__ Y, const float* __restrict__ resid,
    int K, int O)
{
    extern __shared__ __half cs[];
    __half* Wh = cs;
    __half* Wl = cs + CTILE;
    __half* Bbuf[2] = { cs + 2 * CTILE, cs + 3 * CTILE };

    const int HW = 4096;
    const int b  = blockIdx.z;
    const int o0 = blockIdx.y * 128;
    const int p0 = blockIdx.x * 128;
    const int tid  = threadIdx.x;
    const int w    = tid >> 5;
    const int lane = tid & 31;
    const int grp  = lane >> 2;
    const int tig  = lane & 3;

    const __half* srcB = xt + (size_t)b * HW * K + (size_t)p0 * K;
    const int nk = K >> 6;

    auto stage_B = [&](int kc, int bi) {
        uint32_t d = smem_u32(Bbuf[bi]);
        int k0 = kc * 64;
#pragma unroll
        for (int l = 0; l < 4; l++) {
            int n = tid + l * 256;
            int r = n >> 3, q = n & 7;
            CP_ASYNC16(d + (uint32_t)(r * (CPITCH * 2) + q * 16), srcB + (size_t)r * K + k0 + q * 8);
        }
    };

    float c[16][4];
#pragma unroll
    for (int nt = 0; nt < 16; nt++)
#pragma unroll
        for (int q = 0; q < 4; q++) c[nt][q] = 0.f;

    stage_B(0, 0);
    CP_COMMIT();

    for (int kc = 0; kc < nk; kc++) {
        const int k0 = kc * 64;
        __syncthreads();
        if (kc + 1 < nk) stage_B(kc + 1, (kc + 1) & 1);
        CP_COMMIT();
#pragma unroll
        for (int l = 0; l < 16; l++) {
            int n = tid + l * 256;
            int o = n >> 5, kk = n & 31;
            float2 e = *(const float2*)(W + (size_t)(o0 + o) * K + k0 + 2 * kk);
            uint32_t h, lo;
            split2h(e.x, e.y, h, lo);
            *(uint32_t*)(Wh + o * CPITCH + 2 * kk) = h;
            *(uint32_t*)(Wl + o * CPITCH + 2 * kk) = lo;
        }
        CP_WAIT1();
        __syncthreads();

        const __half* B = Bbuf[kc & 1];
#pragma unroll
        for (int kt = 0; kt < 4; kt++) {
            const int wo = (w * 16 + grp) * CPITCH + kt * 16 + 2 * tig;
            uint32_t ah0 = *(const uint32_t*)(Wh + wo);
            uint32_t ah1 = *(const uint32_t*)(Wh + wo + 8 * CPITCH);
            uint32_t ah2 = *(const uint32_t*)(Wh + wo + 8);
            uint32_t ah3 = *(const uint32_t*)(Wh + wo + 8 * CPITCH + 8);
            uint32_t al0 = *(const uint32_t*)(Wl + wo);
            uint32_t al1 = *(const uint32_t*)(Wl + wo + 8 * CPITCH);
            uint32_t al2 = *(const uint32_t*)(Wl + wo + 8);
            uint32_t al3 = *(const uint32_t*)(Wl + wo + 8 * CPITCH + 8);
#pragma unroll
            for (int nt = 0; nt < 16; nt++) {
                const __half* bp = B + (nt * 8 + grp) * CPITCH + kt * 16 + 2 * tig;
                uint32_t bh0 = *(const uint32_t*)bp;
                uint32_t bh1 = *(const uint32_t*)(bp + 8);
                mma_f16(c[nt][0], c[nt][1], c[nt][2], c[nt][3], ah0, ah1, ah2, ah3, bh0, bh1);
                mma_f16(c[nt][0], c[nt][1], c[nt][2], c[nt][3], al0, al1, al2, al3, bh0, bh1);
            }
        }
    }

    const int o_r0 = o0 + w * 16 + grp;
    const int o_r1 = o_r0 + 8;
    float s0  = gam[o_r0] * rsqrtf(var[o_r0] + EPS);
    float sh0 = beta[o_r0] - mean[o_r0] * s0;
    float bi0 = bias[o_r0];
    float s1  = gam[o_r1] * rsqrtf(var[o_r1] + EPS);
    float sh1 = beta[o_r1] - mean[o_r1] * s1;
    float bi1 = bias[o_r1];
    float* y0 = Y + (size_t)b * O * HW + (size_t)o_r0 * HW + p0;
    float* y1 = Y + (size_t)b * O * HW + (size_t)o_r1 * HW + p0;
    const float* rs0 = resid ? resid + (size_t)b * O * HW + (size_t)o_r0 * HW + p0 : nullptr;
    const float* rs1 = resid ? resid + (size_t)b * O * HW + (size_t)o_r1 * HW + p0 : nullptr;
#pragma unroll
    for (int nt = 0; nt < 16; nt++) {
        int p = nt * 8 + 2 * tig;
        float v00 = fmaxf((c[nt][0] + bi0) * s0 + sh0, 0.f);
        float v01 = fmaxf((c[nt][1] + bi0) * s0 + sh0, 0.f);
        float v10 = fmaxf((c[nt][2] + bi1) * s1 + sh1, 0.f);
        float v11 = fmaxf((c[nt][3] + bi1) * s1 + sh1, 0.f);
        if (rs0) {
            float2 r0v = *(const float2*)(rs0 + p);
            float2 r1v = *(const float2*)(rs1 + p);
            v00 += r0v.x; v01 += r0v.y; v10 += r1v.x; v11 += r1v.y;
        }
        *(float2*)(y0 + p) = make_float2(v00, v01);
        *(float2*)(y1 + p) = make_float2(v10, v11);
    }
}

// ---------------- attention: gemm1 3-product (B1 split), gemm2 2-product (B2 single) ----------------
#define B1PITCH 136
#define B2PITCH 72
#define B1ELEMS (64 * B1PITCH)
#define B2ELEMS (128 * B2PITCH)
#define STG_ELEMS (2 * B1ELEMS + B2ELEMS)   // 26624 elems = 53248 B
#define ATTN_SMEM (2 * STG_ELEMS * 2)       // 106496 B

__global__ __launch_bounds__(256) void attn_mma_kernel(
    const float* __restrict__ x1,
    const __half* __restrict__ x2h, const __half* __restrict__ x2l,
    const __half* __restrict__ x3, float* __restrict__ out)
{
    extern __shared__ __half smh[];

    const int tid  = threadIdx.x;
    const int w    = tid >> 5;
    const int lane = tid & 31;
    const int grp  = lane >> 2;
    const int tig  = lane & 3;
    const int b    = blockIdx.y;
    const int i0   = blockIdx.x * 128;
    const int r0   = w * 16 + grp;

    uint32_t ahi[8][4], alo[8][4];
    {
        const float* a0p = x1 + (size_t)b * 524288 + (size_t)(i0 + r0) * 128;
        const float* a1p = a0p + 8 * 128;
#pragma unroll
        for (int kt = 0; kt < 8; kt++) {
            float2 e00 = *(const float2*)(a0p + kt * 16 + 2 * tig);
            float2 e01 = *(const float2*)(a0p + kt * 16 + 2 * tig + 8);
            float2 e10 = *(const float2*)(a1p + kt * 16 + 2 * tig);
            float2 e11 = *(const float2*)(a1p + kt * 16 + 2 * tig + 8);
            split2h(e00.x, e00.y, ahi[kt][0], alo[kt][0]);
            split2h(e10.x, e10.y, ahi[kt][1], alo[kt][1]);
            split2h(e01.x, e01.y, ahi[kt][2], alo[kt][2]);
            split2h(e11.x, e11.y, ahi[kt][3], alo[kt][3]);
        }
    }

    const __half* X2Hb = x2h + (size_t)b * 131072;
    const __half* X2Lb = x2l + (size_t)b * 131072;
    const __half* X3b  = x3  + (size_t)b * 131072;

    const uint32_t smbase = smem_u32(smh);

    auto stage = [&](int ch, int st) {
        const uint32_t s0  = smbase + (uint32_t)st * (STG_ELEMS * 2);
        const uint32_t b1h = s0;
        const uint32_t b1l = s0 + B1ELEMS * 2;
        const uint32_t b2  = s0 + 2 * B1ELEMS * 2;
        const int j0 = ch * 64;
#pragma unroll
        for (int l = 0; l < 4; l++) {
            int n = tid + l * 256;
            {
                int r = n >> 4, p = n & 15;
                uint32_t off = (uint32_t)(r * (B1PITCH * 2) + p * 16);
                CP_ASYNC16(b1h + off, X2Hb + (size_t)(j0 + r) * 128 + p * 8);
                CP_ASYNC16(b1l + off, X2Lb + (size_t)(j0 + r) * 128 + p * 8);
            }
            {
                int r = n >> 3, p = n & 7;
                uint32_t off = (uint32_t)(r * (B2PITCH * 2) + p * 16);
                CP_ASYNC16(b2 + off, X3b + (size_t)r * 1024 + j0 + p * 8);
            }
        }
    };

    float o[16][4];
#pragma unroll
    for (int nt = 0; nt < 16; nt++)
#pragma unroll
        for (int q = 0; q < 4; q++) o[nt][q] = 0.f;
    float m0 = -CUDART_INF_F, m1 = -CUDART_INF_F, l0 = 0.f, l1 = 0.f;

    stage(0, 0);
    CP_COMMIT();

    for (int ch = 0; ch < 16; ch++) {
        if (ch) __syncthreads();
        if (ch + 1 < 16) stage(ch + 1, (ch + 1) & 1);
        CP_COMMIT();
        CP_WAIT1();
        __syncthreads();

        const __half* B1H = smh + (ch & 1) * STG_ELEMS;
        const __half* B1L = B1H + B1ELEMS;
        const __half* B2  = B1H + 2 * B1ELEMS;

        float s[8][4];
#pragma unroll
        for (int nt = 0; nt < 8; nt++)
#pragma unroll
            for (int q = 0; q < 4; q++) s[nt][q] = 0.f;

#pragma unroll
        for (int kt = 0; kt < 8; kt++) {
#pragma unroll
            for (int nt = 0; nt < 8; nt++) {
                const __half* bp  = B1H + (nt * 8 + grp) * B1PITCH + kt * 16 + 2 * tig;
                const __half* bpl = B1L + (nt * 8 + grp) * B1PITCH + kt * 16 + 2 * tig;
                uint32_t bh0 = *(const uint32_t*)bp;
                uint32_t bh1 = *(const uint32_t*)(bp + 8);
                uint32_t bl0 = *(const uint32_t*)bpl;
                uint32_t bl1 = *(const uint32_t*)(bpl + 8);
                mma_f16(s[nt][0], s[nt][1], s[nt][2], s[nt][3],
                        ahi[kt][0], ahi[kt][1], ahi[kt][2], ahi[kt][3], bh0, bh1);
                mma_f16(s[nt][0], s[nt][1], s[nt][2], s[nt][3],
                        ahi[kt][0], ahi[kt][1], ahi[kt][2], ahi[kt][3], bl0, bl1);
                mma_f16(s[nt][0], s[nt][1], s[nt][2], s[nt][3],
                        alo[kt][0], alo[kt][1], alo[kt][2], alo[kt][3], bh0, bh1);
            }
        }

        float mx0 = s[0][0], mx1 = s[0][2];
#pragma unroll
        for (int nt = 0; nt < 8; nt++) {
            mx0 = fmaxf(mx0, fmaxf(s[nt][0], s[nt][1]));
            mx1 = fmaxf(mx1, fmaxf(s[nt][2], s[nt][3]));
        }
        mx0 = fmaxf(mx0, __shfl_xor_sync(0xffffffffu, mx0, 1));
        mx0 = fmaxf(mx0, __shfl_xor_sync(0xffffffffu, mx0, 2));
        mx1 = fmaxf(mx1, __shfl_xor_sync(0xffffffffu, mx1, 1));
        mx1 = fmaxf(mx1, __shfl_xor_sync(0xffffffffu, mx1, 2));
        float n0 = fmaxf(m0, mx0), n1 = fmaxf(m1, mx1);
        float f0 = __expf(m0 - n0), f1 = __expf(m1 - n1);
        m0 = n0; m1 = n1;
        float ps0 = 0.f, ps1 = 0.f;
#pragma unroll
        for (int nt = 0; nt < 8; nt++) {
            s[nt][0] = __expf(s[nt][0] - n0);
            s[nt][1] = __expf(s[nt][1] - n0);
            s[nt][2] = __expf(s[nt][2] - n1);
            s[nt][3] = __expf(s[nt][3] - n1);
            ps0 += s[nt][0] + s[nt][1];
            ps1 += s[nt][2] + s[nt][3];
        }
        ps0 += __shfl_xor_sync(0xffffffffu, ps0, 1);
        ps0 += __shfl_xor_sync(0xffffffffu, ps0, 2);
        ps1 += __shfl_xor_sync(0xffffffffu, ps1, 1);
        ps1 += __shfl_xor_sync(0xffffffffu, ps1, 2);
        l0 = l0 * f0 + ps0;
        l1 = l1 * f1 + ps1;
#pragma unroll
        for (int nt = 0; nt < 16; nt++) {
            o[nt][0] *= f0; o[nt][1] *= f0;
            o[nt][2] *= f1; o[nt][3] *= f1;
        }

        uint32_t phi[4][4], plo[4][4];
#pragma unroll
        for (int kt = 0; kt < 4; kt++) {
            split2h(s[2 * kt][0],     s[2 * kt][1],     phi[kt][0], plo[kt][0]);
            split2h(s[2 * kt][2],     s[2 * kt][3],     phi[kt][1], plo[kt][1]);
            split2h(s[2 * kt + 1][0], s[2 * kt + 1][1], phi[kt][2], plo[kt][2]);
            split2h(s[2 * kt + 1][2], s[2 * kt + 1][3], phi[kt][3], plo[kt][3]);
        }

        // gemm2: O += (Phi + Plo) x B2 (B2 single fp16)
#pragma unroll
        for (int kt = 0; kt < 4; kt++) {
#pragma unroll
            for (int nt = 0; nt < 16; nt++) {
                const __half* bp = B2 + (nt * 8 + grp) * B2PITCH + kt * 16 + 2 * tig;
                uint32_t bh0 = *(const uint32_t*)bp;
                uint32_t bh1 = *(const uint32_t*)(bp + 8);
                mma_f16(o[nt][0], o[nt][1], o[nt][2], o[nt][3],
                        phi[kt][0], phi[kt][1], phi[kt][2], phi[kt][3], bh0, bh1);
                mma_f16(o[nt][0], o[nt][1], o[nt][2], o[nt][3],
                        plo[kt][0], plo[kt][1], plo[kt][2], plo[kt][3], bh0, bh1);
            }
        }
    }

    float inv0 = 1.0f / l0, inv1 = 1.0f / l1;
    float* og0 = out + (size_t)b * 524288 + (size_t)(i0 + r0) * 128;
    float* og1 = og0 + 8 * 128;
#pragma unroll
    for (int nt = 0; nt < 16; nt++) {
        *(float2*)(og0 + nt * 8 + 2 * tig) = make_float2(o[nt][0] * inv0, o[nt][1] * inv0);
        *(float2*)(og1 + nt * 8 + 2 * tig) = make_float2(o[nt][2] * inv1, o[nt][3] * inv1);
    }
}

// ---------------- launcher ----------------
extern "C" void kernel_launch(void* const* d_in, const int* in_sizes, int n_in,
                              void* d_out, int out_size)
{
    const float* a       = (const float*)d_in[0];
    const float* conv1_w = (const float*)d_in[1];
    const float* conv1_b = (const float*)d_in[2];
    const float* bn1_g   = (const float*)d_in[3];
    const float* bn1_b   = (const float*)d_in[4];
    const float* bn1_m   = (const float*)d_in[5];
    const float* bn1_v   = (const float*)d_in[6];
    const float* conv2_w = (const float*)d_in[7];
    const float* conv2_b = (const float*)d_in[8];
    const float* bn2_g   = (const float*)d_in[9];
    const float* bn2_b   = (const float*)d_in[10];
    const float* bn2_m   = (const float*)d_in[11];
    const float* bn2_v   = (const float*)d_in[12];
    const float* conv3_w = (const float*)d_in[13];
    const float* conv3_b = (const float*)d_in[14];
    const float* bn3_g   = (const float*)d_in[15];
    const float* bn3_b   = (const float*)d_in[16];
    const float* bn3_m   = (const float*)d_in[17];
    const float* bn3_v   = (const float*)d_in[18];
    float* out = (float*)d_out;

    float *p_x1, *p_y2, *p_attn;
    __half *p_x2h, *p_x2l, *p_x3, *p_at;
    cudaGetSymbolAddress((void**)&p_x1,   g_x1);
    cudaGetSymbolAddress((void**)&p_y2,   g_y2);
    cudaGetSymbolAddress((void**)&p_attn, g_attn);
    cudaGetSymbolAddress((void**)&p_x2h,  g_x2t_hi);
    cudaGetSymbolAddress((void**)&p_x2l,  g_x2t_lo);
    cudaGetSymbolAddress((void**)&p_x3,   g_x3t);
    cudaGetSymbolAddress((void**)&p_at,   g_at);

    cudaFuncSetAttribute(attn_mma_kernel,   cudaFuncAttributeMaxDynamicSharedMemorySize, ATTN_SMEM);
    cudaFuncSetAttribute(conv_mma_kernel,   cudaFuncAttributeMaxDynamicSharedMemorySize, CONV_SMEM);
    cudaFuncSetAttribute(conv12_mma_kernel, cudaFuncAttributeMaxDynamicSharedMemorySize, C12_SMEM);

    dim3 blk(256);

    // transpose a (NCHW [256][4096]) -> [b][p][c] fp16 (shared by conv1 & conv2)
    transpose_split_kernel<<<dim3(128, 8, 8), dim3(32, 8)>>>(a, p_at, 256, 4096);

    // conv1 + conv2 merged
    conv12_mma_kernel<<<dim3(32, 1, 8), blk, C12_SMEM>>>(
        p_at,
        conv1_w, conv1_b, bn1_g, bn1_b, bn1_m, bn1_v, p_x1,
        conv2_w, conv2_b, bn2_g, bn2_b, bn2_m, bn2_v, p_y2);

    // fused maxpool + attention operand layouts
    pool_split_kernel<<<dim3(32, 4, 8), blk>>>(p_y2, p_x2h, p_x2l, p_x3);

    // attention
    attn_mma_kernel<<<dim3(32, 8), blk, ATTN_SMEM>>>(
        p_x1, p_x2h, p_x2l, p_x3, p_attn);

    // conv3 input: NCHW view [c=128][p=4096] of raw-reshaped attn; transpose -> [p][c] fp16
    transpose_split_kernel<<<dim3(128, 4, 8), dim3(32, 8)>>>(p_attn, p_at, 128, 4096);

    // conv3 + residual -> out
    conv_mma_kernel<<<dim3(32, 2, 8), blk, CONV_SMEM>>>(
        p_at, conv3_w, conv3_b, bn3_g, bn3_b, bn3_m, bn3_v, out, a, 128, 256);
}

// round 14
// speedup vs baseline: 1.1534x; 1.1534x over previous
#include <cuda_runtime.h>
#include <cuda_bf16.h>
#include <math_constants.h>
#include <cstdint>

#define EPS 1e-5f

// ---------------- scratch ----------------
__device__ float g_x1[8 * 128 * 4096];
__device__ float g_y2[8 * 128 * 4096];
__device__ float g_attn[8 * 128 * 4096];
__device__ __nv_bfloat16 g_x2t_hi[8 * 1024 * 128];  // [b][j][c] = X2[c][j]
__device__ __nv_bfloat16 g_x2t_lo[8 * 1024 * 128];
__device__ __nv_bfloat16 g_x3t_hi[8 * 128 * 1024];  // [b][c][j] = X3[j][c] = pooledflat[j*128+c]
__device__ __nv_bfloat16 g_x3t_lo[8 * 128 * 1024];
__device__ __nv_bfloat16 g_at_hi[8 * 4096 * 256];   // transposed conv input [b][p][c]
__device__ __nv_bfloat16 g_at_lo[8 * 4096 * 256];

// ---------------- helpers ----------------
__device__ __forceinline__ void mma_bf16(float& c0, float& c1, float& c2, float& c3,
                                         uint32_t a0, uint32_t a1, uint32_t a2, uint32_t a3,
                                         uint32_t b0, uint32_t b1)
{
    asm volatile("mma.sync.aligned.m16n8k16.row.col.f32.bf16.bf16.f32 "
                 "{%0,%1,%2,%3}, {%4,%5,%6,%7}, {%8,%9}, {%0,%1,%2,%3};"
                 : "+f"(c0), "+f"(c1), "+f"(c2), "+f"(c3)
                 : "r"(a0), "r"(a1), "r"(a2), "r"(a3), "r"(b0), "r"(b1));
}
__device__ __forceinline__ void split2(float e0, float e1, uint32_t& hi, uint32_t& lo)
{
    asm("cvt.rn.bf16x2.f32 %0, %1, %2;" : "=r"(hi) : "f"(e1), "f"(e0));
    float f0h = __uint_as_float(hi << 16);
    float f1h = __uint_as_float(hi & 0xffff0000u);
    asm("cvt.rn.bf16x2.f32 %0, %1, %2;" : "=r"(lo) : "f"(e1 - f1h), "f"(e0 - f0h));
}
__device__ __forceinline__ void split1(float v, __nv_bfloat16& h, __nv_bfloat16& l)
{
    h = __float2bfloat16(v);
    l = __float2bfloat16(v - __bfloat162float(h));
}
__device__ __forceinline__ uint32_t smem_u32(const void* p) {
    uint32_t a;
    asm("{ .reg .u64 t; cvta.to.shared.u64 t, %1; cvt.u32.u64 %0, t; }" : "=r"(a) : "l"(p));
    return a;
}
#define CP_ASYNC16(dst, src) asm volatile("cp.async.cg.shared.global [%0], [%1], 16;" :: "r"(dst), "l"(src))
#define CP_COMMIT()          asm volatile("cp.async.commit_group;" ::: "memory")
#define CP_WAIT1()           asm volatile("cp.async.wait_group 1;" ::: "memory")

// ---------------- fused maxpool + attention operand layouts (validated R8) ----------------
__global__ __launch_bounds__(256) void pool_split_kernel(
    const float* __restrict__ y2,
    __nv_bfloat16* __restrict__ x2h, __nv_bfloat16* __restrict__ x2l,
    __nv_bfloat16* __restrict__ x3h, __nv_bfloat16* __restrict__ x3l)
{
    __shared__ float t[32][33];
    const int p  = blockIdx.x;
    const int c0 = blockIdx.y * 32;
    const int b  = blockIdx.z;
    const int tid = threadIdx.x;
    const int q   = tid & 31;
    const int ccb = tid >> 5;

    const float* src = y2 + (size_t)b * 128 * 4096;
    const int r0 = 2 * p - 1;
#pragma unroll
    for (int k = 0; k < 4; k++) {
        int cc = ccb + 8 * k;
        const float* row = src + (size_t)(c0 + cc) * 4096;
        float m = -CUDART_INF_F;
#pragma unroll
        for (int dr = 0; dr < 3; dr++) {
            int r = r0 + dr;
            if (r < 0 || r >= 64) continue;
#pragma unroll
            for (int dc = 0; dc < 3; dc++) {
                int col = 2 * q - 1 + dc;
                if (col < 0 || col >= 64) continue;
                m = fmaxf(m, row[r * 64 + col]);
            }
        }
        t[cc][q] = m;
    }
    __syncthreads();

    const int cc2 = tid & 31;
#pragma unroll
    for (int k = 0; k < 4; k++) {
        int q2 = ccb + 8 * k;
        __nv_bfloat16 h, l;
        split1(t[cc2][q2], h, l);
        size_t o2 = (size_t)b * 131072 + (size_t)(p * 32 + q2) * 128 + c0 + cc2;
        x2h[o2] = h; x2l[o2] = l;
        int c3 = 32 * (p & 3) + q2;
        int j3 = (c0 + cc2) * 8 + (p >> 2);
        size_t o3 = (size_t)b * 131072 + (size_t)c3 * 1024 + j3;
        x3h[o3] = h; x3l[o3] = l;
    }
}

// ---------------- transpose + bf16 split: NCHW [b][C][P] -> [b][p][c] ----------------
__global__ void transpose_split_kernel(const float* __restrict__ src_,
                                       __nv_bfloat16* __restrict__ oh, __nv_bfloat16* __restrict__ ol,
                                       int C, int P)
{
    __shared__ float t[32][33];
    int b = blockIdx.z;
    int p0 = blockIdx.x * 32, c0 = blockIdx.y * 32;
    int tx = threadIdx.x, ty = threadIdx.y;
    const float* src = src_ + (size_t)b * C * P;
#pragma unroll
    for (int k = 0; k < 4; k++)
        t[ty + 8 * k][tx] = src[(size_t)(c0 + ty + 8 * k) * P + p0 + tx];
    __syncthreads();
#pragma unroll
    for (int k = 0; k < 4; k++) {
        float v = t[tx][ty + 8 * k];
        __nv_bfloat16 h, l;
        split1(v, h, l);
        size_t o = (size_t)b * C * P + (size_t)(p0 + ty + 8 * k) * C + c0 + tx;
        oh[o] = h; ol[o] = l;
    }
}

#define CPITCH 72
#define CTILE (128 * CPITCH)

// ---------------- conv1+conv2 merged (validated R12) ----------------
#define C12_SMEM (8 * CTILE * 2)

__global__ __launch_bounds__(256) void conv12_mma_kernel(
    const __nv_bfloat16* __restrict__ xth, const __nv_bfloat16* __restrict__ xtl,
    const float* __restrict__ W1, const float* __restrict__ bias1,
    const float* __restrict__ gam1, const float* __restrict__ beta1,
    const float* __restrict__ mean1, const float* __restrict__ var1,
    float* __restrict__ Y1,
    const float* __restrict__ W2, const float* __restrict__ bias2,
    const float* __restrict__ gam2, const float* __restrict__ beta2,
    const float* __restrict__ mean2, const float* __restrict__ var2,
    float* __restrict__ Y2)
{
    extern __shared__ __nv_bfloat16 cs[];
    __nv_bfloat16* W1h = cs;
    __nv_bfloat16* W1l = cs + CTILE;
    __nv_bfloat16* W2h = cs + 2 * CTILE;
    __nv_bfloat16* W2l = cs + 3 * CTILE;
    __nv_bfloat16* Bbuf[2][2] = {
        { cs + 4 * CTILE, cs + 5 * CTILE },
        { cs + 6 * CTILE, cs + 7 * CTILE } };

    const int HW = 4096;
    const int K  = 256;
    const int b  = blockIdx.z;
    const int p0 = blockIdx.x * 128;
    const int tid  = threadIdx.x;
    const int w    = tid >> 5;
    const int lane = tid & 31;
    const int grp  = lane >> 2;
    const int tig  = lane & 3;

    const __nv_bfloat16* srcH = xth + (size_t)b * HW * K + (size_t)p0 * K;
    const __nv_bfloat16* srcL = xtl + (size_t)b * HW * K + (size_t)p0 * K;

    auto stage_B = [&](int kc, int bi) {
        uint32_t dh = smem_u32(Bbuf[bi][0]);
        uint32_t dl = smem_u32(Bbuf[bi][1]);
        int k0 = kc * 64;
#pragma unroll
        for (int l = 0; l < 4; l++) {
            int n = tid + l * 256;
            int r = n >> 3, q = n & 7;
            uint32_t off = (uint32_t)(r * (CPITCH * 2) + q * 16);
            CP_ASYNC16(dh + off, srcH + (size_t)r * K + k0 + q * 8);
            CP_ASYNC16(dl + off, srcL + (size_t)r * K + k0 + q * 8);
        }
    };

    float c1[16][4], c2[16][4];
#pragma unroll
    for (int nt = 0; nt < 16; nt++)
#pragma unroll
        for (int q = 0; q < 4; q++) { c1[nt][q] = 0.f; c2[nt][q] = 0.f; }

    stage_B(0, 0);
    CP_COMMIT();

    for (int kc = 0; kc < 4; kc++) {
        const int k0 = kc * 64;
        __syncthreads();
        if (kc + 1 < 4) stage_B(kc + 1, (kc + 1) & 1);
        CP_COMMIT();
#pragma unroll
        for (int l = 0; l < 16; l++) {
            int n = tid + l * 256;
            int o = n >> 5, kk = n & 31;
            float2 e1 = *(const float2*)(W1 + (size_t)o * K + k0 + 2 * kk);
            float2 e2 = *(const float2*)(W2 + (size_t)o * K + k0 + 2 * kk);
            uint32_t h, lo;
            split2(e1.x, e1.y, h, lo);
            *(uint32_t*)(W1h + o * CPITCH + 2 * kk) = h;
            *(uint32_t*)(W1l + o * CPITCH + 2 * kk) = lo;
            split2(e2.x, e2.y, h, lo);
            *(uint32_t*)(W2h + o * CPITCH + 2 * kk) = h;
            *(uint32_t*)(W2l + o * CPITCH + 2 * kk) = lo;
        }
        CP_WAIT1();
        __syncthreads();

        const __nv_bfloat16* Bh = Bbuf[kc & 1][0];
        const __nv_bfloat16* Bl = Bbuf[kc & 1][1];
#pragma unroll
        for (int kt = 0; kt < 4; kt++) {
            const int wo = (w * 16 + grp) * CPITCH + kt * 16 + 2 * tig;
            uint32_t a1h0 = *(const uint32_t*)(W1h + wo);
            uint32_t a1h1 = *(const uint32_t*)(W1h + wo + 8 * CPITCH);
            uint32_t a1h2 = *(const uint32_t*)(W1h + wo + 8);
            uint32_t a1h3 = *(const uint32_t*)(W1h + wo + 8 * CPITCH + 8);
            uint32_t a1l0 = *(const uint32_t*)(W1l + wo);
            uint32_t a1l1 = *(const uint32_t*)(W1l + wo + 8 * CPITCH);
            uint32_t a1l2 = *(const uint32_t*)(W1l + wo + 8);
            uint32_t a1l3 = *(const uint32_t*)(W1l + wo + 8 * CPITCH + 8);
            uint32_t a2h0 = *(const uint32_t*)(W2h + wo);
            uint32_t a2h1 = *(const uint32_t*)(W2h + wo + 8 * CPITCH);
            uint32_t a2h2 = *(const uint32_t*)(W2h + wo + 8);
            uint32_t a2h3 = *(const uint32_t*)(W2h + wo + 8 * CPITCH + 8);
            uint32_t a2l0 = *(const uint32_t*)(W2l + wo);
            uint32_t a2l1 = *(const uint32_t*)(W2l + wo + 8 * CPITCH);
            uint32_t a2l2 = *(const uint32_t*)(W2l + wo + 8);
            uint32_t a2l3 = *(const uint32_t*)(W2l + wo + 8 * CPITCH + 8);
#pragma unroll
            for (int nt = 0; nt < 16; nt++) {
                const __nv_bfloat16* bp  = Bh + (nt * 8 + grp) * CPITCH + kt * 16 + 2 * tig;
                const __nv_bfloat16* bpl = Bl + (nt * 8 + grp) * CPITCH + kt * 16 + 2 * tig;
                uint32_t bh0 = *(const uint32_t*)bp;
                uint32_t bh1 = *(const uint32_t*)(bp + 8);
                uint32_t bl0 = *(const uint32_t*)bpl;
                uint32_t bl1 = *(const uint32_t*)(bpl + 8);
                mma_bf16(c1[nt][0], c1[nt][1], c1[nt][2], c1[nt][3], a1h0, a1h1, a1h2, a1h3, bh0, bh1);
                mma_bf16(c1[nt][0], c1[nt][1], c1[nt][2], c1[nt][3], a1h0, a1h1, a1h2, a1h3, bl0, bl1);
                mma_bf16(c1[nt][0], c1[nt][1], c1[nt][2], c1[nt][3], a1l0, a1l1, a1l2, a1l3, bh0, bh1);
                mma_bf16(c2[nt][0], c2[nt][1], c2[nt][2], c2[nt][3], a2h0, a2h1, a2h2, a2h3, bh0, bh1);
                mma_bf16(c2[nt][0], c2[nt][1], c2[nt][2], c2[nt][3], a2h0, a2h1, a2h2, a2h3, bl0, bl1);
                mma_bf16(c2[nt][0], c2[nt][1], c2[nt][2], c2[nt][3], a2l0, a2l1, a2l2, a2l3, bh0, bh1);
            }
        }
    }

    const int o_r0 = w * 16 + grp;
    const int o_r1 = o_r0 + 8;
#pragma unroll
    for (int sel = 0; sel < 2; sel++) {
        const float* bias = sel ? bias2 : bias1;
        const float* gam  = sel ? gam2 : gam1;
        const float* beta = sel ? beta2 : beta1;
        const float* mean = sel ? mean2 : mean1;
        const float* var  = sel ? var2 : var1;
        float* Y          = sel ? Y2 : Y1;
        float (*cc)[4]    = sel ? c2 : c1;
        float s0  = gam[o_r0] * rsqrtf(var[o_r0] + EPS);
        float sh0 = beta[o_r0] - mean[o_r0] * s0;
        float bi0 = bias[o_r0];
        float s1  = gam[o_r1] * rsqrtf(var[o_r1] + EPS);
        float sh1 = beta[o_r1] - mean[o_r1] * s1;
        float bi1 = bias[o_r1];
        float* y0 = Y + (size_t)b * 128 * HW + (size_t)o_r0 * HW + p0;
        float* y1 = Y + (size_t)b * 128 * HW + (size_t)o_r1 * HW + p0;
#pragma unroll
        for (int nt = 0; nt < 16; nt++) {
            int p = nt * 8 + 2 * tig;
            *(float2*)(y0 + p) = make_float2(
                fmaxf((cc[nt][0] + bi0) * s0 + sh0, 0.f),
                fmaxf((cc[nt][1] + bi0) * s0 + sh0, 0.f));
            *(float2*)(y1 + p) = make_float2(
                fmaxf((cc[nt][2] + bi1) * s1 + sh1, 0.f),
                fmaxf((cc[nt][3] + bi1) * s1 + sh1, 0.f));
        }
    }
}

// ---------------- conv3 (validated R8/R12) ----------------
#define CONV_SMEM (6 * CTILE * 2)

__global__ __launch_bounds__(256) void conv_mma_kernel(
    const __nv_bfloat16* __restrict__ xth, const __nv_bfloat16* __restrict__ xtl,
    const float* __restrict__ W, const float* __restrict__ bias,
    const float* __restrict__ gam, const float* __restrict__ beta,
    const float* __restrict__ mean, const float* __restrict__ var,
    float* __restrict__ Y, const float* __restrict__ resid,
    int K, int O)
{
    extern __shared__ __nv_bfloat16 cs[];
    __nv_bfloat16* Wh = cs;
    __nv_bfloat16* Wl = cs + CTILE;
    __nv_bfloat16* Bbuf[2][2] = {
        { cs + 2 * CTILE, cs + 3 * CTILE },
        { cs + 4 * CTILE, cs + 5 * CTILE } };

    const int HW = 4096;
    const int b  = blockIdx.z;
    const int o0 = blockIdx.y * 128;
    const int p0 = blockIdx.x * 128;
    const int tid  = threadIdx.x;
    const int w    = tid >> 5;
    const int lane = tid & 31;
    const int grp  = lane >> 2;
    const int tig  = lane & 3;

    const __nv_bfloat16* srcH = xth + (size_t)b * HW * K + (size_t)p0 * K;
    const __nv_bfloat16* srcL = xtl + (size_t)b * HW * K + (size_t)p0 * K;

    const int nk = K >> 6;

    auto stage_B = [&](int kc, int bi) {
        uint32_t dh = smem_u32(Bbuf[bi][0]);
        uint32_t dl = smem_u32(Bbuf[bi][1]);
        int k0 = kc * 64;
#pragma unroll
        for (int l = 0; l < 4; l++) {
            int n = tid + l * 256;
            int r = n >> 3, q = n & 7;
            uint32_t off = (uint32_t)(r * (CPITCH * 2) + q * 16);
            CP_ASYNC16(dh + off, srcH + (size_t)r * K + k0 + q * 8);
            CP_ASYNC16(dl + off, srcL + (size_t)r * K + k0 + q * 8);
        }
    };

    float c[16][4];
#pragma unroll
    for (int nt = 0; nt < 16; nt++)
#pragma unroll
        for (int q = 0; q < 4; q++) c[nt][q] = 0.f;

    stage_B(0, 0);
    CP_COMMIT();

    for (int kc = 0; kc < nk; kc++) {
        const int k0 = kc * 64;
        __syncthreads();
        if (kc + 1 < nk) stage_B(kc + 1, (kc + 1) & 1);
        CP_COMMIT();
#pragma unroll
        for (int l = 0; l < 16; l++) {
            int n = tid + l * 256;
            int o = n >> 5, kk = n & 31;
            float2 e = *(const float2*)(W + (size_t)(o0 + o) * K + k0 + 2 * kk);
            uint32_t h, lo;
            split2(e.x, e.y, h, lo);
            *(uint32_t*)(Wh + o * CPITCH + 2 * kk) = h;
            *(uint32_t*)(Wl + o * CPITCH + 2 * kk) = lo;
        }
        CP_WAIT1();
        __syncthreads();

        const __nv_bfloat16* Bh = Bbuf[kc & 1][0];
        const __nv_bfloat16* Bl = Bbuf[kc & 1][1];
#pragma unroll
        for (int kt = 0; kt < 4; kt++) {
            const int wo = (w * 16 + grp) * CPITCH + kt * 16 + 2 * tig;
            uint32_t ah0 = *(const uint32_t*)(Wh + wo);
            uint32_t ah1 = *(const uint32_t*)(Wh + wo + 8 * CPITCH);
            uint32_t ah2 = *(const uint32_t*)(Wh + wo + 8);
            uint32_t ah3 = *(const uint32_t*)(Wh + wo + 8 * CPITCH + 8);
            uint32_t al0 = *(const uint32_t*)(Wl + wo);
            uint32_t al1 = *(const uint32_t*)(Wl + wo + 8 * CPITCH);
            uint32_t al2 = *(const uint32_t*)(Wl + wo + 8);
            uint32_t al3 = *(const uint32_t*)(Wl + wo + 8 * CPITCH + 8);
#pragma unroll
            for (int nt = 0; nt < 16; nt++) {
                const __nv_bfloat16* bp  = Bh + (nt * 8 + grp) * CPITCH + kt * 16 + 2 * tig;
                const __nv_bfloat16* bpl = Bl + (nt * 8 + grp) * CPITCH + kt * 16 + 2 * tig;
                uint32_t bh0 = *(const uint32_t*)bp;
                uint32_t bh1 = *(const uint32_t*)(bp + 8);
                uint32_t bl0 = *(const uint32_t*)bpl;
                uint32_t bl1 = *(const uint32_t*)(bpl + 8);
                mma_bf16(c[nt][0], c[nt][1], c[nt][2], c[nt][3], ah0, ah1, ah2, ah3, bh0, bh1);
                mma_bf16(c[nt][0], c[nt][1], c[nt][2], c[nt][3], ah0, ah1, ah2, ah3, bl0, bl1);
                mma_bf16(c[nt][0], c[nt][1], c[nt][2], c[nt][3], al0, al1, al2, al3, bh0, bh1);
            }
        }
    }

    const int o_r0 = o0 + w * 16 + grp;
    const int o_r1 = o_r0 + 8;
    float s0  = gam[o_r0] * rsqrtf(var[o_r0] + EPS);
    float sh0 = beta[o_r0] - mean[o_r0] * s0;
    float bi0 = bias[o_r0];
    float s1  = gam[o_r1] * rsqrtf(var[o_r1] + EPS);
    float sh1 = beta[o_r1] - mean[o_r1] * s1;
    float bi1 = bias[o_r1];
    float* y0 = Y + (size_t)b * O * HW + (size_t)o_r0 * HW + p0;
    float* y1 = Y + (size_t)b * O * HW + (size_t)o_r1 * HW + p0;
    const float* rs0 = resid ? resid + (size_t)b * O * HW + (size_t)o_r0 * HW + p0 : nullptr;
    const float* rs1 = resid ? resid + (size_t)b * O * HW + (size_t)o_r1 * HW + p0 : nullptr;
#pragma unroll
    for (int nt = 0; nt < 16; nt++) {
        int p = nt * 8 + 2 * tig;
        float v00 = fmaxf((c[nt][0] + bi0) * s0 + sh0, 0.f);
        float v01 = fmaxf((c[nt][1] + bi0) * s0 + sh0, 0.f);
        float v10 = fmaxf((c[nt][2] + bi1) * s1 + sh1, 0.f);
        float v11 = fmaxf((c[nt][3] + bi1) * s1 + sh1, 0.f);
        if (rs0) {
            float2 r0v = *(const float2*)(rs0 + p);
            float2 r1v = *(const float2*)(rs1 + p);
            v00 += r0v.x; v01 += r0v.y; v10 += r1v.x; v11 += r1v.y;
        }
        *(float2*)(y0 + p) = make_float2(v00, v01);
        *(float2*)(y1 + p) = make_float2(v10, v11);
    }
}

// ---------------- attention: R12 math + anti-phase warp groups + triple buffer ----------------
#define B1PITCH 136
#define B2PITCH 72
#define B1ELEMS (64 * B1PITCH)
#define B2ELEMS (128 * B2PITCH)
#define STG_ELEMS (2 * B1ELEMS + 2 * B2ELEMS)   // 35840 elems
#define ATTN_SMEM (3 * STG_ELEMS * 2)           // 215040 B

__global__ __launch_bounds__(256) void attn_mma_kernel(
    const float* __restrict__ x1,
    const __nv_bfloat16* __restrict__ x2h, const __nv_bfloat16* __restrict__ x2l,
    const __nv_bfloat16* __restrict__ x3h, const __nv_bfloat16* __restrict__ x3l,
    float* __restrict__ out)
{
    extern __shared__ __nv_bfloat16 smb[];

    const int tid  = threadIdx.x;
    const int w    = tid >> 5;
    const int lane = tid & 31;
    const int grp  = lane >> 2;
    const int tig  = lane & 3;
    const int b    = blockIdx.y;
    const int i0   = blockIdx.x * 128;
    const int r0   = w * 16 + grp;

    uint32_t ahi[8][4], alo[8][4];
    {
        const float* a0p = x1 + (size_t)b * 524288 + (size_t)(i0 + r0) * 128;
        const float* a1p = a0p + 8 * 128;
#pragma unroll
        for (int kt = 0; kt < 8; kt++) {
            float2 e00 = *(const float2*)(a0p + kt * 16 + 2 * tig);
            float2 e01 = *(const float2*)(a0p + kt * 16 + 2 * tig + 8);
            float2 e10 = *(const float2*)(a1p + kt * 16 + 2 * tig);
            float2 e11 = *(const float2*)(a1p + kt * 16 + 2 * tig + 8);
            split2(e00.x, e00.y, ahi[kt][0], alo[kt][0]);
            split2(e10.x, e10.y, ahi[kt][1], alo[kt][1]);
            split2(e01.x, e01.y, ahi[kt][2], alo[kt][2]);
            split2(e11.x, e11.y, ahi[kt][3], alo[kt][3]);
        }
    }

    const __nv_bfloat16* X2Hb = x2h + (size_t)b * 131072;
    const __nv_bfloat16* X2Lb = x2l + (size_t)b * 131072;
    const __nv_bfloat16* X3Hb = x3h + (size_t)b * 131072;
    const __nv_bfloat16* X3Lb = x3l + (size_t)b * 131072;

    const uint32_t smbase = smem_u32(smb);

    auto stage = [&](int ch) {
        const int st = ch % 3;
        const uint32_t s0  = smbase + (uint32_t)st * (STG_ELEMS * 2);
        const uint32_t b1h = s0;
        const uint32_t b1l = s0 + B1ELEMS * 2;
        const uint32_t b2h = s0 + 2 * B1ELEMS * 2;
        const uint32_t b2l = b2h + B2ELEMS * 2;
        const int j0 = ch * 64;
#pragma unroll
        for (int l = 0; l < 4; l++) {
            int n = tid + l * 256;
            {
                int r = n >> 4, p = n & 15;
                uint32_t off = (uint32_t)(r * (B1PITCH * 2) + p * 16);
                CP_ASYNC16(b1h + off, X2Hb + (size_t)(j0 + r) * 128 + p * 8);
                CP_ASYNC16(b1l + off, X2Lb + (size_t)(j0 + r) * 128 + p * 8);
            }
            {
                int r = n >> 3, p = n & 7;
                uint32_t off = (uint32_t)(r * (B2PITCH * 2) + p * 16);
                CP_ASYNC16(b2h + off, X3Hb + (size_t)r * 1024 + j0 + p * 8);
                CP_ASYNC16(b2l + off, X3Lb + (size_t)r * 1024 + j0 + p * 8);
            }
        }
    };

    float s_cur[8][4], s_next[8][4];
    float o[16][4];
#pragma unroll
    for (int nt = 0; nt < 16; nt++)
#pragma unroll
        for (int q = 0; q < 4; q++) o[nt][q] = 0.f;
    float m0 = -CUDART_INF_F, m1 = -CUDART_INF_F, l0 = 0.f, l1 = 0.f;
    uint32_t phi[4][4], plo[4][4];

    auto gemm1 = [&](float (*s)[4], int ch) {
        const __nv_bfloat16* B1H = smb + (ch % 3) * STG_ELEMS;
        const __nv_bfloat16* B1L = B1H + B1ELEMS;
#pragma unroll
        for (int nt = 0; nt < 8; nt++)
#pragma unroll
            for (int q = 0; q < 4; q++) s[nt][q] = 0.f;
#pragma unroll
        for (int kt = 0; kt < 8; kt++) {
#pragma unroll
            for (int nt = 0; nt < 8; nt++) {
                const __nv_bfloat16* bp  = B1H + (nt * 8 + grp) * B1PITCH + kt * 16 + 2 * tig;
                const __nv_bfloat16* bpl = B1L + (nt * 8 + grp) * B1PITCH + kt * 16 + 2 * tig;
                uint32_t bh0 = *(const uint32_t*)bp;
                uint32_t bh1 = *(const uint32_t*)(bp + 8);
                uint32_t bl0 = *(const uint32_t*)bpl;
                uint32_t bl1 = *(const uint32_t*)(bpl + 8);
                mma_bf16(s[nt][0], s[nt][1], s[nt][2], s[nt][3],
                         ahi[kt][0], ahi[kt][1], ahi[kt][2], ahi[kt][3], bh0, bh1);
                mma_bf16(s[nt][0], s[nt][1], s[nt][2], s[nt][3],
                         ahi[kt][0], ahi[kt][1], ahi[kt][2], ahi[kt][3], bl0, bl1);
                mma_bf16(s[nt][0], s[nt][1], s[nt][2], s[nt][3],
                         alo[kt][0], alo[kt][1], alo[kt][2], alo[kt][3], bh0, bh1);
            }
        }
    };

    auto softmax_pack = [&]() {
        float mx0 = s_cur[0][0], mx1 = s_cur[0][2];
#pragma unroll
        for (int nt = 0; nt < 8; nt++) {
            mx0 = fmaxf(mx0, fmaxf(s_cur[nt][0], s_cur[nt][1]));
            mx1 = fmaxf(mx1, fmaxf(s_cur[nt][2], s_cur[nt][3]));
        }
        mx0 = fmaxf(mx0, __shfl_xor_sync(0xffffffffu, mx0, 1));
        mx0 = fmaxf(mx0, __shfl_xor_sync(0xffffffffu, mx0, 2));
        mx1 = fmaxf(mx1, __shfl_xor_sync(0xffffffffu, mx1, 1));
        mx1 = fmaxf(mx1, __shfl_xor_sync(0xffffffffu, mx1, 2));
        float n0 = fmaxf(m0, mx0), n1 = fmaxf(m1, mx1);
        float f0 = __expf(m0 - n0), f1 = __expf(m1 - n1);
        m0 = n0; m1 = n1;
        float ps0 = 0.f, ps1 = 0.f;
#pragma unroll
        for (int nt = 0; nt < 8; nt++) {
            s_cur[nt][0] = __expf(s_cur[nt][0] - n0);
            s_cur[nt][1] = __expf(s_cur[nt][1] - n0);
            s_cur[nt][2] = __expf(s_cur[nt][2] - n1);
            s_cur[nt][3] = __expf(s_cur[nt][3] - n1);
            ps0 += s_cur[nt][0] + s_cur[nt][1];
            ps1 += s_cur[nt][2] + s_cur[nt][3];
        }
        ps0 += __shfl_xor_sync(0xffffffffu, ps0, 1);
        ps0 += __shfl_xor_sync(0xffffffffu, ps0, 2);
        ps1 += __shfl_xor_sync(0xffffffffu, ps1, 1);
        ps1 += __shfl_xor_sync(0xffffffffu, ps1, 2);
        l0 = l0 * f0 + ps0;
        l1 = l1 * f1 + ps1;
#pragma unroll
        for (int nt = 0; nt < 16; nt++) {
            o[nt][0] *= f0; o[nt][1] *= f0;
            o[nt][2] *= f1; o[nt][3] *= f1;
        }
#pragma unroll
        for (int kt = 0; kt < 4; kt++) {
            split2(s_cur[2 * kt][0],     s_cur[2 * kt][1],     phi[kt][0], plo[kt][0]);
            split2(s_cur[2 * kt][2],     s_cur[2 * kt][3],     phi[kt][1], plo[kt][1]);
            split2(s_cur[2 * kt + 1][0], s_cur[2 * kt + 1][1], phi[kt][2], plo[kt][2]);
            split2(s_cur[2 * kt + 1][2], s_cur[2 * kt + 1][3], phi[kt][3], plo[kt][3]);
        }
    };

    auto gemm2 = [&](int ch) {
        const __nv_bfloat16* B2H = smb + (ch % 3) * STG_ELEMS + 2 * B1ELEMS;
        const __nv_bfloat16* B2L = B2H + B2ELEMS;
#pragma unroll
        for (int kt = 0; kt < 4; kt++) {
#pragma unroll
            for (int nt = 0; nt < 16; nt++) {
                const __nv_bfloat16* bp  = B2H + (nt * 8 + grp) * B2PITCH + kt * 16 + 2 * tig;
                const __nv_bfloat16* bpl = B2L + (nt * 8 + grp) * B2PITCH + kt * 16 + 2 * tig;
                uint32_t bh0 = *(const uint32_t*)bp;
                uint32_t bh1 = *(const uint32_t*)(bp + 8);
                uint32_t bl0 = *(const uint32_t*)bpl;
                uint32_t bl1 = *(const uint32_t*)(bpl + 8);
                mma_bf16(o[nt][0], o[nt][1], o[nt][2], o[nt][3],
                         phi[kt][0], phi[kt][1], phi[kt][2], phi[kt][3], bh0, bh1);
                mma_bf16(o[nt][0], o[nt][1], o[nt][2], o[nt][3],
                         phi[kt][0], phi[kt][1], phi[kt][2], phi[kt][3], bl0, bl1);
                mma_bf16(o[nt][0], o[nt][1], o[nt][2], o[nt][3],
                         plo[kt][0], plo[kt][1], plo[kt][2], plo[kt][3], bh0, bh1);
            }
        }
    };

    // prologue: stages 0 and 1 in flight; compute S(0)
    stage(0); CP_COMMIT();
    stage(1); CP_COMMIT();
    CP_WAIT1();
    __syncthreads();
    gemm1(s_cur, 0);

    for (int ch = 0; ch < 16; ch++) {
        __syncthreads();                 // all warps done with buf[(ch-1)%3] (gemm2(ch-1))
        if (ch + 2 < 16) stage(ch + 2);
        CP_COMMIT();
        CP_WAIT1();                      // stage(ch+1) arrived
        __syncthreads();                 // cp.async writes visible
        if (w < 4) {                     // group X: gemm first
            if (ch + 1 < 16) gemm1(s_next, ch + 1);
            softmax_pack();
            gemm2(ch);
        } else {                         // group Y: softmax first (anti-phase)
            softmax_pack();
            gemm2(ch);
            if (ch + 1 < 16) gemm1(s_next, ch + 1);
        }
        if (ch + 1 < 16) {
#pragma unroll
            for (int nt = 0; nt < 8; nt++)
#pragma unroll
                for (int q = 0; q < 4; q++) s_cur[nt][q] = s_next[nt][q];
        }
    }

    float inv0 = 1.0f / l0, inv1 = 1.0f / l1;
    float* og0 = out + (size_t)b * 524288 + (size_t)(i0 + r0) * 128;
    float* og1 = og0 + 8 * 128;
#pragma unroll
    for (int nt = 0; nt < 16; nt++) {
        *(float2*)(og0 + nt * 8 + 2 * tig) = make_float2(o[nt][0] * inv0, o[nt][1] * inv0);
        *(float2*)(og1 + nt * 8 + 2 * tig) = make_float2(o[nt][2] * inv1, o[nt][3] * inv1);
    }
}

// ---------------- launcher ----------------
extern "C" void kernel_launch(void* const* d_in, const int* in_sizes, int n_in,
                              void* d_out, int out_size)
{
    const float* a       = (const float*)d_in[0];
    const float* conv1_w = (const float*)d_in[1];
    const float* conv1_b = (const float*)d_in[2];
    const float* bn1_g   = (const float*)d_in[3];
    const float* bn1_b   = (const float*)d_in[4];
    const float* bn1_m   = (const float*)d_in[5];
    const float* bn1_v   = (const float*)d_in[6];
    const float* conv2_w = (const float*)d_in[7];
    const float* conv2_b = (const float*)d_in[8];
    const float* bn2_g   = (const float*)d_in[9];
    const float* bn2_b   = (const float*)d_in[10];
    const float* bn2_m   = (const float*)d_in[11];
    const float* bn2_v   = (const float*)d_in[12];
    const float* conv3_w = (const float*)d_in[13];
    const float* conv3_b = (const float*)d_in[14];
    const float* bn3_g   = (const float*)d_in[15];
    const float* bn3_b   = (const float*)d_in[16];
    const float* bn3_m   = (const float*)d_in[17];
    const float* bn3_v   = (const float*)d_in[18];
    float* out = (float*)d_out;

    float *p_x1, *p_y2, *p_attn;
    __nv_bfloat16 *p_x2h, *p_x2l, *p_x3h, *p_x3l, *p_ath, *p_atl;
    cudaGetSymbolAddress((void**)&p_x1,   g_x1);
    cudaGetSymbolAddress((void**)&p_y2,   g_y2);
    cudaGetSymbolAddress((void**)&p_attn, g_attn);
    cudaGetSymbolAddress((void**)&p_x2h,  g_x2t_hi);
    cudaGetSymbolAddress((void**)&p_x2l,  g_x2t_lo);
    cudaGetSymbolAddress((void**)&p_x3h,  g_x3t_hi);
    cudaGetSymbolAddress((void**)&p_x3l,  g_x3t_lo);
    cudaGetSymbolAddress((void**)&p_ath,  g_at_hi);
    cudaGetSymbolAddress((void**)&p_atl,  g_at_lo);

    cudaFuncSetAttribute(attn_mma_kernel,   cudaFuncAttributeMaxDynamicSharedMemorySize, ATTN_SMEM);
    cudaFuncSetAttribute(conv_mma_kernel,   cudaFuncAttributeMaxDynamicSharedMemorySize, CONV_SMEM);
    cudaFuncSetAttribute(conv12_mma_kernel, cudaFuncAttributeMaxDynamicSharedMemorySize, C12_SMEM);

    dim3 blk(256);

    transpose_split_kernel<<<dim3(128, 8, 8), dim3(32, 8)>>>(a, p_ath, p_atl, 256, 4096);

    conv12_mma_kernel<<<dim3(32, 1, 8), blk, C12_SMEM>>>(
        p_ath, p_atl,
        conv1_w, conv1_b, bn1_g, bn1_b, bn1_m, bn1_v, p_x1,
        conv2_w, conv2_b, bn2_g, bn2_b, bn2_m, bn2_v, p_y2);

    pool_split_kernel<<<dim3(32, 4, 8), blk>>>(p_y2, p_x2h, p_x2l, p_x3h, p_x3l);

    attn_mma_kernel<<<dim3(32, 8), blk, ATTN_SMEM>>>(
        p_x1, p_x2h, p_x2l, p_x3h, p_x3l, p_attn);

    transpose_split_kernel<<<dim3(128, 4, 8), dim3(32, 8)>>>(p_attn, p_ath, p_atl, 128, 4096);

    conv_mma_kernel<<<dim3(32, 2, 8), blk, CONV_SMEM>>>(
        p_ath, p_atl,
        conv3_w, conv3_b, bn3_g, bn3_b, bn3_m, bn3_v, out, a, 128, 256);
}

// round 15
// speedup vs baseline: 1.2985x; 1.1258x over previous
#include <cuda_runtime.h>
#include <cuda_bf16.h>
#include <math_constants.h>
#include <cstdint>

#define EPS 1e-5f

// ---------------- scratch ----------------
__device__ float g_x1[8 * 128 * 4096];
__device__ float g_y2[8 * 128 * 4096];
__device__ float g_attn[8 * 128 * 4096];
__device__ __nv_bfloat16 g_x2t_hi[8 * 1024 * 128];  // [b][j][c] = X2[c][j]
__device__ __nv_bfloat16 g_x2t_lo[8 * 1024 * 128];
__device__ __nv_bfloat16 g_x3t_hi[8 * 128 * 1024];  // [b][c][j] = X3[j][c] = pooledflat[j*128+c]
__device__ __nv_bfloat16 g_x3t_lo[8 * 128 * 1024];
__device__ __nv_bfloat16 g_at_hi[8 * 4096 * 256];   // transposed conv input [b][p][c]
__device__ __nv_bfloat16 g_at_lo[8 * 4096 * 256];

// ---------------- helpers ----------------
__device__ __forceinline__ void mma_bf16(float& c0, float& c1, float& c2, float& c3,
                                         uint32_t a0, uint32_t a1, uint32_t a2, uint32_t a3,
                                         uint32_t b0, uint32_t b1)
{
    asm volatile("mma.sync.aligned.m16n8k16.row.col.f32.bf16.bf16.f32 "
                 "{%0,%1,%2,%3}, {%4,%5,%6,%7}, {%8,%9}, {%0,%1,%2,%3};"
                 : "+f"(c0), "+f"(c1), "+f"(c2), "+f"(c3)
                 : "r"(a0), "r"(a1), "r"(a2), "r"(a3), "r"(b0), "r"(b1));
}
__device__ __forceinline__ void split2(float e0, float e1, uint32_t& hi, uint32_t& lo)
{
    asm("cvt.rn.bf16x2.f32 %0, %1, %2;" : "=r"(hi) : "f"(e1), "f"(e0));
    float f0h = __uint_as_float(hi << 16);
    float f1h = __uint_as_float(hi & 0xffff0000u);
    asm("cvt.rn.bf16x2.f32 %0, %1, %2;" : "=r"(lo) : "f"(e1 - f1h), "f"(e0 - f0h));
}
__device__ __forceinline__ void split1(float v, __nv_bfloat16& h, __nv_bfloat16& l)
{
    h = __float2bfloat16(v);
    l = __float2bfloat16(v - __bfloat162float(h));
}
__device__ __forceinline__ uint32_t smem_u32(const void* p) {
    uint32_t a;
    asm("{ .reg .u64 t; cvta.to.shared.u64 t, %1; cvt.u32.u64 %0, t; }" : "=r"(a) : "l"(p));
    return a;
}
#define CP_ASYNC16(dst, src) asm volatile("cp.async.cg.shared.global [%0], [%1], 16;" :: "r"(dst), "l"(src))
#define CP_COMMIT()          asm volatile("cp.async.commit_group;" ::: "memory")
#define CP_WAIT1()           asm volatile("cp.async.wait_group 1;" ::: "memory")

// ---------------- fused maxpool + attention operand layouts (validated R8) ----------------
__global__ __launch_bounds__(256) void pool_split_kernel(
    const float* __restrict__ y2,
    __nv_bfloat16* __restrict__ x2h, __nv_bfloat16* __restrict__ x2l,
    __nv_bfloat16* __restrict__ x3h, __nv_bfloat16* __restrict__ x3l)
{
    __shared__ float t[32][33];
    const int p  = blockIdx.x;
    const int c0 = blockIdx.y * 32;
    const int b  = blockIdx.z;
    const int tid = threadIdx.x;
    const int q   = tid & 31;
    const int ccb = tid >> 5;

    const float* src = y2 + (size_t)b * 128 * 4096;
    const int r0 = 2 * p - 1;
#pragma unroll
    for (int k = 0; k < 4; k++) {
        int cc = ccb + 8 * k;
        const float* row = src + (size_t)(c0 + cc) * 4096;
        float m = -CUDART_INF_F;
#pragma unroll
        for (int dr = 0; dr < 3; dr++) {
            int r = r0 + dr;
            if (r < 0 || r >= 64) continue;
#pragma unroll
            for (int dc = 0; dc < 3; dc++) {
                int col = 2 * q - 1 + dc;
                if (col < 0 || col >= 64) continue;
                m = fmaxf(m, row[r * 64 + col]);
            }
        }
        t[cc][q] = m;
    }
    __syncthreads();

    const int cc2 = tid & 31;
#pragma unroll
    for (int k = 0; k < 4; k++) {
        int q2 = ccb + 8 * k;
        __nv_bfloat16 h, l;
        split1(t[cc2][q2], h, l);
        size_t o2 = (size_t)b * 131072 + (size_t)(p * 32 + q2) * 128 + c0 + cc2;
        x2h[o2] = h; x2l[o2] = l;
        int c3 = 32 * (p & 3) + q2;
        int j3 = (c0 + cc2) * 8 + (p >> 2);
        size_t o3 = (size_t)b * 131072 + (size_t)c3 * 1024 + j3;
        x3h[o3] = h; x3l[o3] = l;
    }
}

// ---------------- transpose + bf16 split: NCHW [b][C][P] -> [b][p][c] ----------------
__global__ void transpose_split_kernel(const float* __restrict__ src_,
                                       __nv_bfloat16* __restrict__ oh, __nv_bfloat16* __restrict__ ol,
                                       int C, int P)
{
    __shared__ float t[32][33];
    int b = blockIdx.z;
    int p0 = blockIdx.x * 32, c0 = blockIdx.y * 32;
    int tx = threadIdx.x, ty = threadIdx.y;
    const float* src = src_ + (size_t)b * C * P;
#pragma unroll
    for (int k = 0; k < 4; k++)
        t[ty + 8 * k][tx] = src[(size_t)(c0 + ty + 8 * k) * P + p0 + tx];
    __syncthreads();
#pragma unroll
    for (int k = 0; k < 4; k++) {
        float v = t[tx][ty + 8 * k];
        __nv_bfloat16 h, l;
        split1(v, h, l);
        size_t o = (size_t)b * C * P + (size_t)(p0 + ty + 8 * k) * C + c0 + tx;
        oh[o] = h; ol[o] = l;
    }
}

#define CPITCH 72
#define CTILE (128 * CPITCH)

// ---------------- dual-output conv: two 128-o sets sharing one B operand ----------------
// Set X: WX (128 rows x K), BN paramsX, YX (+residX), rows written at YX + b*O*HW + o*HW.
// Used for conv1+conv2 (different weights, two outputs) AND conv3 (same weight split o 0-127 / 128-255,
// second set passes +128-offset pointers). B = Xt[p][c] bf16 hi/lo, staged once, 6 mma per B-frag.
#define CDUAL_SMEM (8 * CTILE * 2)   // 147456 B

__global__ __launch_bounds__(256) void conv_dual_kernel(
    const __nv_bfloat16* __restrict__ xth, const __nv_bfloat16* __restrict__ xtl,
    const float* __restrict__ W1, const float* __restrict__ bias1,
    const float* __restrict__ gam1, const float* __restrict__ beta1,
    const float* __restrict__ mean1, const float* __restrict__ var1,
    float* __restrict__ Y1, const float* __restrict__ resid1,
    const float* __restrict__ W2, const float* __restrict__ bias2,
    const float* __restrict__ gam2, const float* __restrict__ beta2,
    const float* __restrict__ mean2, const float* __restrict__ var2,
    float* __restrict__ Y2, const float* __restrict__ resid2,
    int K, int O)
{
    extern __shared__ __nv_bfloat16 cs[];
    __nv_bfloat16* W1h = cs;
    __nv_bfloat16* W1l = cs + CTILE;
    __nv_bfloat16* W2h = cs + 2 * CTILE;
    __nv_bfloat16* W2l = cs + 3 * CTILE;
    __nv_bfloat16* Bbuf[2][2] = {
        { cs + 4 * CTILE, cs + 5 * CTILE },
        { cs + 6 * CTILE, cs + 7 * CTILE } };

    const int HW = 4096;
    const int b  = blockIdx.z;
    const int p0 = blockIdx.x * 128;
    const int tid  = threadIdx.x;
    const int w    = tid >> 5;
    const int lane = tid & 31;
    const int grp  = lane >> 2;
    const int tig  = lane & 3;

    const __nv_bfloat16* srcH = xth + (size_t)b * HW * K + (size_t)p0 * K;
    const __nv_bfloat16* srcL = xtl + (size_t)b * HW * K + (size_t)p0 * K;
    const int nk = K >> 6;

    auto stage_B = [&](int kc, int bi) {
        uint32_t dh = smem_u32(Bbuf[bi][0]);
        uint32_t dl = smem_u32(Bbuf[bi][1]);
        int k0 = kc * 64;
#pragma unroll
        for (int l = 0; l < 4; l++) {
            int n = tid + l * 256;
            int r = n >> 3, q = n & 7;
            uint32_t off = (uint32_t)(r * (CPITCH * 2) + q * 16);
            CP_ASYNC16(dh + off, srcH + (size_t)r * K + k0 + q * 8);
            CP_ASYNC16(dl + off, srcL + (size_t)r * K + k0 + q * 8);
        }
    };

    float c1[16][4], c2[16][4];
#pragma unroll
    for (int nt = 0; nt < 16; nt++)
#pragma unroll
        for (int q = 0; q < 4; q++) { c1[nt][q] = 0.f; c2[nt][q] = 0.f; }

    stage_B(0, 0);
    CP_COMMIT();

    for (int kc = 0; kc < nk; kc++) {
        const int k0 = kc * 64;
        __syncthreads();
        if (kc + 1 < nk) stage_B(kc + 1, (kc + 1) & 1);
        CP_COMMIT();
#pragma unroll
        for (int l = 0; l < 16; l++) {
            int n = tid + l * 256;
            int o = n >> 5, kk = n & 31;
            float2 e1 = *(const float2*)(W1 + (size_t)o * K + k0 + 2 * kk);
            float2 e2 = *(const float2*)(W2 + (size_t)o * K + k0 + 2 * kk);
            uint32_t h, lo;
            split2(e1.x, e1.y, h, lo);
            *(uint32_t*)(W1h + o * CPITCH + 2 * kk) = h;
            *(uint32_t*)(W1l + o * CPITCH + 2 * kk) = lo;
            split2(e2.x, e2.y, h, lo);
            *(uint32_t*)(W2h + o * CPITCH + 2 * kk) = h;
            *(uint32_t*)(W2l + o * CPITCH + 2 * kk) = lo;
        }
        CP_WAIT1();
        __syncthreads();

        const __nv_bfloat16* Bh = Bbuf[kc & 1][0];
        const __nv_bfloat16* Bl = Bbuf[kc & 1][1];
#pragma unroll
        for (int kt = 0; kt < 4; kt++) {
            const int wo = (w * 16 + grp) * CPITCH + kt * 16 + 2 * tig;
            uint32_t a1h0 = *(const uint32_t*)(W1h + wo);
            uint32_t a1h1 = *(const uint32_t*)(W1h + wo + 8 * CPITCH);
            uint32_t a1h2 = *(const uint32_t*)(W1h + wo + 8);
            uint32_t a1h3 = *(const uint32_t*)(W1h + wo + 8 * CPITCH + 8);
            uint32_t a1l0 = *(const uint32_t*)(W1l + wo);
            uint32_t a1l1 = *(const uint32_t*)(W1l + wo + 8 * CPITCH);
            uint32_t a1l2 = *(const uint32_t*)(W1l + wo + 8);
            uint32_t a1l3 = *(const uint32_t*)(W1l + wo + 8 * CPITCH + 8);
            uint32_t a2h0 = *(const uint32_t*)(W2h + wo);
            uint32_t a2h1 = *(const uint32_t*)(W2h + wo + 8 * CPITCH);
            uint32_t a2h2 = *(const uint32_t*)(W2h + wo + 8);
            uint32_t a2h3 = *(const uint32_t*)(W2h + wo + 8 * CPITCH + 8);
            uint32_t a2l0 = *(const uint32_t*)(W2l + wo);
            uint32_t a2l1 = *(const uint32_t*)(W2l + wo + 8 * CPITCH);
            uint32_t a2l2 = *(const uint32_t*)(W2l + wo + 8);
            uint32_t a2l3 = *(const uint32_t*)(W2l + wo + 8 * CPITCH + 8);
#pragma unroll
            for (int nt = 0; nt < 16; nt++) {
                const __nv_bfloat16* bp  = Bh + (nt * 8 + grp) * CPITCH + kt * 16 + 2 * tig;
                const __nv_bfloat16* bpl = Bl + (nt * 8 + grp) * CPITCH + kt * 16 + 2 * tig;
                uint32_t bh0 = *(const uint32_t*)bp;
                uint32_t bh1 = *(const uint32_t*)(bp + 8);
                uint32_t bl0 = *(const uint32_t*)bpl;
                uint32_t bl1 = *(const uint32_t*)(bpl + 8);
                mma_bf16(c1[nt][0], c1[nt][1], c1[nt][2], c1[nt][3], a1h0, a1h1, a1h2, a1h3, bh0, bh1);
                mma_bf16(c1[nt][0], c1[nt][1], c1[nt][2], c1[nt][3], a1h0, a1h1, a1h2, a1h3, bl0, bl1);
                mma_bf16(c1[nt][0], c1[nt][1], c1[nt][2], c1[nt][3], a1l0, a1l1, a1l2, a1l3, bh0, bh1);
                mma_bf16(c2[nt][0], c2[nt][1], c2[nt][2], c2[nt][3], a2h0, a2h1, a2h2, a2h3, bh0, bh1);
                mma_bf16(c2[nt][0], c2[nt][1], c2[nt][2], c2[nt][3], a2h0, a2h1, a2h2, a2h3, bl0, bl1);
                mma_bf16(c2[nt][0], c2[nt][1], c2[nt][2], c2[nt][3], a2l0, a2l1, a2l2, a2l3, bh0, bh1);
            }
        }
    }

    const int o_r0 = w * 16 + grp;
    const int o_r1 = o_r0 + 8;
#pragma unroll
    for (int sel = 0; sel < 2; sel++) {
        const float* bias = sel ? bias2 : bias1;
        const float* gam  = sel ? gam2 : gam1;
        const float* beta = sel ? beta2 : beta1;
        const float* mean = sel ? mean2 : mean1;
        const float* var  = sel ? var2 : var1;
        float* Y          = sel ? Y2 : Y1;
        const float* rsd  = sel ? resid2 : resid1;
        float (*cc)[4]    = sel ? c2 : c1;
        float s0  = gam[o_r0] * rsqrtf(var[o_r0] + EPS);
        float sh0 = beta[o_r0] - mean[o_r0] * s0;
        float bi0 = bias[o_r0];
        float s1  = gam[o_r1] * rsqrtf(var[o_r1] + EPS);
        float sh1 = beta[o_r1] - mean[o_r1] * s1;
        float bi1 = bias[o_r1];
        float* y0 = Y + (size_t)b * O * HW + (size_t)o_r0 * HW + p0;
        float* y1 = Y + (size_t)b * O * HW + (size_t)o_r1 * HW + p0;
        const float* rs0 = rsd ? rsd + (size_t)b * O * HW + (size_t)o_r0 * HW + p0 : nullptr;
        const float* rs1 = rsd ? rsd + (size_t)b * O * HW + (size_t)o_r1 * HW + p0 : nullptr;
#pragma unroll
        for (int nt = 0; nt < 16; nt++) {
            int p = nt * 8 + 2 * tig;
            float v00 = fmaxf((cc[nt][0] + bi0) * s0 + sh0, 0.f);
            float v01 = fmaxf((cc[nt][1] + bi0) * s0 + sh0, 0.f);
            float v10 = fmaxf((cc[nt][2] + bi1) * s1 + sh1, 0.f);
            float v11 = fmaxf((cc[nt][3] + bi1) * s1 + sh1, 0.f);
            if (rs0) {
                float2 r0v = *(const float2*)(rs0 + p);
                float2 r1v = *(const float2*)(rs1 + p);
                v00 += r0v.x; v01 += r0v.y; v10 += r1v.x; v11 += r1v.y;
            }
            *(float2*)(y0 + p) = make_float2(v00, v01);
            *(float2*)(y1 + p) = make_float2(v10, v11);
        }
    }
}

// ---------------- attention: R12 math, triple-buffered stages, ONE barrier per chunk ----------------
#define B1PITCH 136
#define B2PITCH 72
#define B1ELEMS (64 * B1PITCH)
#define B2ELEMS (128 * B2PITCH)
#define STG_ELEMS (2 * B1ELEMS + 2 * B2ELEMS)   // 35840 elems = 71680 B
#define ATTN_SMEM (3 * STG_ELEMS * 2)           // 215040 B

__global__ __launch_bounds__(256) void attn_mma_kernel(
    const float* __restrict__ x1,
    const __nv_bfloat16* __restrict__ x2h, const __nv_bfloat16* __restrict__ x2l,
    const __nv_bfloat16* __restrict__ x3h, const __nv_bfloat16* __restrict__ x3l,
    float* __restrict__ out)
{
    extern __shared__ __nv_bfloat16 smb[];

    const int tid  = threadIdx.x;
    const int w    = tid >> 5;
    const int lane = tid & 31;
    const int grp  = lane >> 2;
    const int tig  = lane & 3;
    const int b    = blockIdx.y;
    const int i0   = blockIdx.x * 128;
    const int r0   = w * 16 + grp;

    uint32_t ahi[8][4], alo[8][4];
    {
        const float* a0p = x1 + (size_t)b * 524288 + (size_t)(i0 + r0) * 128;
        const float* a1p = a0p + 8 * 128;
#pragma unroll
        for (int kt = 0; kt < 8; kt++) {
            float2 e00 = *(const float2*)(a0p + kt * 16 + 2 * tig);
            float2 e01 = *(const float2*)(a0p + kt * 16 + 2 * tig + 8);
            float2 e10 = *(const float2*)(a1p + kt * 16 + 2 * tig);
            float2 e11 = *(const float2*)(a1p + kt * 16 + 2 * tig + 8);
            split2(e00.x, e00.y, ahi[kt][0], alo[kt][0]);
            split2(e10.x, e10.y, ahi[kt][1], alo[kt][1]);
            split2(e01.x, e01.y, ahi[kt][2], alo[kt][2]);
            split2(e11.x, e11.y, ahi[kt][3], alo[kt][3]);
        }
    }

    const __nv_bfloat16* X2Hb = x2h + (size_t)b * 131072;
    const __nv_bfloat16* X2Lb = x2l + (size_t)b * 131072;
    const __nv_bfloat16* X3Hb = x3h + (size_t)b * 131072;
    const __nv_bfloat16* X3Lb = x3l + (size_t)b * 131072;

    const uint32_t smbase = smem_u32(smb);

    auto stage = [&](int ch) {
        const int st = ch % 3;
        const uint32_t s0  = smbase + (uint32_t)st * (STG_ELEMS * 2);
        const uint32_t b1h = s0;
        const uint32_t b1l = s0 + B1ELEMS * 2;
        const uint32_t b2h = s0 + 2 * B1ELEMS * 2;
        const uint32_t b2l = b2h + B2ELEMS * 2;
        const int j0 = ch * 64;
#pragma unroll
        for (int l = 0; l < 4; l++) {
            int n = tid + l * 256;
            {
                int r = n >> 4, p = n & 15;
                uint32_t off = (uint32_t)(r * (B1PITCH * 2) + p * 16);
                CP_ASYNC16(b1h + off, X2Hb + (size_t)(j0 + r) * 128 + p * 8);
                CP_ASYNC16(b1l + off, X2Lb + (size_t)(j0 + r) * 128 + p * 8);
            }
            {
                int r = n >> 3, p = n & 7;
                uint32_t off = (uint32_t)(r * (B2PITCH * 2) + p * 16);
                CP_ASYNC16(b2h + off, X3Hb + (size_t)r * 1024 + j0 + p * 8);
                CP_ASYNC16(b2l + off, X3Lb + (size_t)r * 1024 + j0 + p * 8);
            }
        }
    };

    float o[16][4];
#pragma unroll
    for (int nt = 0; nt < 16; nt++)
#pragma unroll
        for (int q = 0; q < 4; q++) o[nt][q] = 0.f;
    float m0 = -CUDART_INF_F, m1 = -CUDART_INF_F, l0 = 0.f, l1 = 0.f;

    stage(0); CP_COMMIT();
    stage(1); CP_COMMIT();

    for (int ch = 0; ch < 16; ch++) {
        CP_WAIT1();          // buf ch complete (in-flight: {ch, ch+1} -> leaves ch+1)
        __syncthreads();     // visibility of all threads' cp.async + all warps done with buf (ch-1)%3

        const __nv_bfloat16* B1H = smb + (ch % 3) * STG_ELEMS;
        const __nv_bfloat16* B1L = B1H + B1ELEMS;
        const __nv_bfloat16* B2H = B1H + 2 * B1ELEMS;
        const __nv_bfloat16* B2L = B2H + B2ELEMS;

        // ---- gemm1: s[i 16][j 64] ----
        float s[8][4];
#pragma unroll
        for (int nt = 0; nt < 8; nt++)
#pragma unroll
            for (int q = 0; q < 4; q++) s[nt][q] = 0.f;

#pragma unroll
        for (int kt = 0; kt < 8; kt++) {
#pragma unroll
            for (int nt = 0; nt < 8; nt++) {
                const __nv_bfloat16* bp  = B1H + (nt * 8 + grp) * B1PITCH + kt * 16 + 2 * tig;
                const __nv_bfloat16* bpl = B1L + (nt * 8 + grp) * B1PITCH + kt * 16 + 2 * tig;
                uint32_t bh0 = *(const uint32_t*)bp;
                uint32_t bh1 = *(const uint32_t*)(bp + 8);
                uint32_t bl0 = *(const uint32_t*)bpl;
                uint32_t bl1 = *(const uint32_t*)(bpl + 8);
                mma_bf16(s[nt][0], s[nt][1], s[nt][2], s[nt][3],
                         ahi[kt][0], ahi[kt][1], ahi[kt][2], ahi[kt][3], bh0, bh1);
                mma_bf16(s[nt][0], s[nt][1], s[nt][2], s[nt][3],
                         ahi[kt][0], ahi[kt][1], ahi[kt][2], ahi[kt][3], bl0, bl1);
                mma_bf16(s[nt][0], s[nt][1], s[nt][2], s[nt][3],
                         alo[kt][0], alo[kt][1], alo[kt][2], alo[kt][3], bh0, bh1);
            }
        }

        // ---- online softmax (rows r0, r0+8) ----
        float mx0 = s[0][0], mx1 = s[0][2];
#pragma unroll
        for (int nt = 0; nt < 8; nt++) {
            mx0 = fmaxf(mx0, fmaxf(s[nt][0], s[nt][1]));
            mx1 = fmaxf(mx1, fmaxf(s[nt][2], s[nt][3]));
        }
        mx0 = fmaxf(mx0, __shfl_xor_sync(0xffffffffu, mx0, 1));
        mx0 = fmaxf(mx0, __shfl_xor_sync(0xffffffffu, mx0, 2));
        mx1 = fmaxf(mx1, __shfl_xor_sync(0xffffffffu, mx1, 1));
        mx1 = fmaxf(mx1, __shfl_xor_sync(0xffffffffu, mx1, 2));
        float n0 = fmaxf(m0, mx0), n1 = fmaxf(m1, mx1);
        float f0 = __expf(m0 - n0), f1 = __expf(m1 - n1);
        m0 = n0; m1 = n1;
        float ps0 = 0.f, ps1 = 0.f;
#pragma unroll
        for (int nt = 0; nt < 8; nt++) {
            s[nt][0] = __expf(s[nt][0] - n0);
            s[nt][1] = __expf(s[nt][1] - n0);
            s[nt][2] = __expf(s[nt][2] - n1);
            s[nt][3] = __expf(s[nt][3] - n1);
            ps0 += s[nt][0] + s[nt][1];
            ps1 += s[nt][2] + s[nt][3];
        }
        ps0 += __shfl_xor_sync(0xffffffffu, ps0, 1);
        ps0 += __shfl_xor_sync(0xffffffffu, ps0, 2);
        ps1 += __shfl_xor_sync(0xffffffffu, ps1, 1);
        ps1 += __shfl_xor_sync(0xffffffffu, ps1, 2);
        l0 = l0 * f0 + ps0;
        l1 = l1 * f1 + ps1;
#pragma unroll
        for (int nt = 0; nt < 16; nt++) {
            o[nt][0] *= f0; o[nt][1] *= f0;
            o[nt][2] *= f1; o[nt][3] *= f1;
        }

        uint32_t phi[4][4], plo[4][4];
#pragma unroll
        for (int kt = 0; kt < 4; kt++) {
            split2(s[2 * kt][0],     s[2 * kt][1],     phi[kt][0], plo[kt][0]);
            split2(s[2 * kt][2],     s[2 * kt][3],     phi[kt][1], plo[kt][1]);
            split2(s[2 * kt + 1][0], s[2 * kt + 1][1], phi[kt][2], plo[kt][2]);
            split2(s[2 * kt + 1][2], s[2 * kt + 1][3], phi[kt][3], plo[kt][3]);
        }

        // ---- gemm2 ----
#pragma unroll
        for (int kt = 0; kt < 4; kt++) {
#pragma unroll
            for (int nt = 0; nt < 16; nt++) {
                const __nv_bfloat16* bp  = B2H + (nt * 8 + grp) * B2PITCH + kt * 16 + 2 * tig;
                const __nv_bfloat16* bpl = B2L + (nt * 8 + grp) * B2PITCH + kt * 16 + 2 * tig;
                uint32_t bh0 = *(const uint32_t*)bp;
                uint32_t bh1 = *(const uint32_t*)(bp + 8);
                uint32_t bl0 = *(const uint32_t*)bpl;
                uint32_t bl1 = *(const uint32_t*)(bpl + 8);
                mma_bf16(o[nt][0], o[nt][1], o[nt][2], o[nt][3],
                         phi[kt][0], phi[kt][1], phi[kt][2], phi[kt][3], bh0, bh1);
                mma_bf16(o[nt][0], o[nt][1], o[nt][2], o[nt][3],
                         phi[kt][0], phi[kt][1], phi[kt][2], phi[kt][3], bl0, bl1);
                mma_bf16(o[nt][0], o[nt][1], o[nt][2], o[nt][3],
                         plo[kt][0], plo[kt][1], plo[kt][2], plo[kt][3], bh0, bh1);
            }
        }

        // prefetch chunk ch+2 into buf (ch+2)%3 (safe: all warps passed this chunk's barrier,
        // so compute(ch-1) reading (ch-1)%3 = (ch+2)%3 is globally complete)
        if (ch + 2 < 16) stage(ch + 2);
        CP_COMMIT();
    }

    float inv0 = 1.0f / l0, inv1 = 1.0f / l1;
    float* og0 = out + (size_t)b * 524288 + (size_t)(i0 + r0) * 128;
    float* og1 = og0 + 8 * 128;
#pragma unroll
    for (int nt = 0; nt < 16; nt++) {
        *(float2*)(og0 + nt * 8 + 2 * tig) = make_float2(o[nt][0] * inv0, o[nt][1] * inv0);
        *(float2*)(og1 + nt * 8 + 2 * tig) = make_float2(o[nt][2] * inv1, o[nt][3] * inv1);
    }
}

// ---------------- launcher ----------------
extern "C" void kernel_launch(void* const* d_in, const int* in_sizes, int n_in,
                              void* d_out, int out_size)
{
    const float* a       = (const float*)d_in[0];
    const float* conv1_w = (const float*)d_in[1];
    const float* conv1_b = (const float*)d_in[2];
    const float* bn1_g   = (const float*)d_in[3];
    const float* bn1_b   = (const float*)d_in[4];
    const float* bn1_m   = (const float*)d_in[5];
    const float* bn1_v   = (const float*)d_in[6];
    const float* conv2_w = (const float*)d_in[7];
    const float* conv2_b = (const float*)d_in[8];
    const float* bn2_g   = (const float*)d_in[9];
    const float* bn2_b   = (const float*)d_in[10];
    const float* bn2_m   = (const float*)d_in[11];
    const float* bn2_v   = (const float*)d_in[12];
    const float* conv3_w = (const float*)d_in[13];
    const float* conv3_b = (const float*)d_in[14];
    const float* bn3_g   = (const float*)d_in[15];
    const float* bn3_b   = (const float*)d_in[16];
    const float* bn3_m   = (const float*)d_in[17];
    const float* bn3_v   = (const float*)d_in[18];
    float* out = (float*)d_out;

    float *p_x1, *p_y2, *p_attn;
    __nv_bfloat16 *p_x2h, *p_x2l, *p_x3h, *p_x3l, *p_ath, *p_atl;
    cudaGetSymbolAddress((void**)&p_x1,   g_x1);
    cudaGetSymbolAddress((void**)&p_y2,   g_y2);
    cudaGetSymbolAddress((void**)&p_attn, g_attn);
    cudaGetSymbolAddress((void**)&p_x2h,  g_x2t_hi);
    cudaGetSymbolAddress((void**)&p_x2l,  g_x2t_lo);
    cudaGetSymbolAddress((void**)&p_x3h,  g_x3t_hi);
    cudaGetSymbolAddress((void**)&p_x3l,  g_x3t_lo);
    cudaGetSymbolAddress((void**)&p_ath,  g_at_hi);
    cudaGetSymbolAddress((void**)&p_atl,  g_at_lo);

    cudaFuncSetAttribute(attn_mma_kernel,  cudaFuncAttributeMaxDynamicSharedMemorySize, ATTN_SMEM);
    cudaFuncSetAttribute(conv_dual_kernel, cudaFuncAttributeMaxDynamicSharedMemorySize, CDUAL_SMEM);

    dim3 blk(256);

    // transpose+split a (NCHW [256][4096]) -> [b][p][c] bf16 (shared by conv1 & conv2)
    transpose_split_kernel<<<dim3(128, 8, 8), dim3(32, 8)>>>(a, p_ath, p_atl, 256, 4096);

    // conv1 + conv2 merged (two weight sets, shared B), O=128 each
    conv_dual_kernel<<<dim3(32, 1, 8), blk, CDUAL_SMEM>>>(
        p_ath, p_atl,
        conv1_w, conv1_b, bn1_g, bn1_b, bn1_m, bn1_v, p_x1, nullptr,
        conv2_w, conv2_b, bn2_g, bn2_b, bn2_m, bn2_v, p_y2, nullptr,
        256, 128);

    // fused maxpool + attention operand layouts
    pool_split_kernel<<<dim3(32, 4, 8), blk>>>(p_y2, p_x2h, p_x2l, p_x3h, p_x3l);

    // attention
    attn_mma_kernel<<<dim3(32, 8), blk, ATTN_SMEM>>>(
        p_x1, p_x2h, p_x2l, p_x3h, p_x3l, p_attn);

    // conv3 input: NCHW view [c=128][p=4096] of raw-reshaped attn; transpose -> [p][c] bf16
    transpose_split_kernel<<<dim3(128, 4, 8), dim3(32, 8)>>>(p_attn, p_ath, p_atl, 128, 4096);

    // conv3 merged o-halves: set A = rows 0-127, set B = rows 128-255 (offset pointers), O=256
    conv_dual_kernel<<<dim3(32, 1, 8), blk, CDUAL_SMEM>>>(
        p_ath, p_atl,
        conv3_w,             conv3_b,       bn3_g,       bn3_b,       bn3_m,       bn3_v,
        out,                 a,
        conv3_w + 128 * 128, conv3_b + 128, bn3_g + 128, bn3_b + 128, bn3_m + 128, bn3_v + 128,
        out + 128 * 4096,    a + 128 * 4096,
        128, 256);
}

// round 16
// speedup vs baseline: 1.3295x; 1.0239x over previous
#include <cuda_runtime.h>
#include <cuda_bf16.h>
#include <math_constants.h>
#include <cstdint>

#define EPS 1e-5f

// ---------------- scratch ----------------
__device__ float g_x1[8 * 128 * 4096];
__device__ float g_y2[8 * 128 * 4096];
__device__ float g_attn[8 * 128 * 4096];
__device__ __nv_bfloat16 g_x2t_hi[8 * 1024 * 128];
__device__ __nv_bfloat16 g_x2t_lo[8 * 1024 * 128];
__device__ __nv_bfloat16 g_x3t_hi[8 * 128 * 1024];
__device__ __nv_bfloat16 g_x3t_lo[8 * 128 * 1024];
__device__ __nv_bfloat16 g_at_hi[8 * 4096 * 256];
__device__ __nv_bfloat16 g_at_lo[8 * 4096 * 256];

// ---------------- helpers ----------------
__device__ __forceinline__ void mma_bf16(float& c0, float& c1, float& c2, float& c3,
                                         uint32_t a0, uint32_t a1, uint32_t a2, uint32_t a3,
                                         uint32_t b0, uint32_t b1)
{
    asm volatile("mma.sync.aligned.m16n8k16.row.col.f32.bf16.bf16.f32 "
                 "{%0,%1,%2,%3}, {%4,%5,%6,%7}, {%8,%9}, {%0,%1,%2,%3};"
                 : "+f"(c0), "+f"(c1), "+f"(c2), "+f"(c3)
                 : "r"(a0), "r"(a1), "r"(a2), "r"(a3), "r"(b0), "r"(b1));
}
__device__ __forceinline__ void ldsm4(uint32_t& r0, uint32_t& r1, uint32_t& r2, uint32_t& r3,
                                      uint32_t addr)
{
    asm volatile("ldmatrix.sync.aligned.m8n8.x4.shared.b16 {%0,%1,%2,%3}, [%4];"
                 : "=r"(r0), "=r"(r1), "=r"(r2), "=r"(r3) : "r"(addr));
}
__device__ __forceinline__ void split2(float e0, float e1, uint32_t& hi, uint32_t& lo)
{
    asm("cvt.rn.bf16x2.f32 %0, %1, %2;" : "=r"(hi) : "f"(e1), "f"(e0));
    float f0h = __uint_as_float(hi << 16);
    float f1h = __uint_as_float(hi & 0xffff0000u);
    asm("cvt.rn.bf16x2.f32 %0, %1, %2;" : "=r"(lo) : "f"(e1 - f1h), "f"(e0 - f0h));
}
__device__ __forceinline__ void split1(float v, __nv_bfloat16& h, __nv_bfloat16& l)
{
    h = __float2bfloat16(v);
    l = __float2bfloat16(v - __bfloat162float(h));
}
__device__ __forceinline__ uint32_t smem_u32(const void* p) {
    uint32_t a;
    asm("{ .reg .u64 t; cvta.to.shared.u64 t, %1; cvt.u32.u64 %0, t; }" : "=r"(a) : "l"(p));
    return a;
}
#define CP_ASYNC16(dst, src) asm volatile("cp.async.cg.shared.global [%0], [%1], 16;" :: "r"(dst), "l"(src))
#define CP_COMMIT()          asm volatile("cp.async.commit_group;" ::: "memory")
#define CP_WAIT1()           asm volatile("cp.async.wait_group 1;" ::: "memory")

// ---------------- fused maxpool + attention operand layouts (validated R8) ----------------
__global__ __launch_bounds__(256) void pool_split_kernel(
    const float* __restrict__ y2,
    __nv_bfloat16* __restrict__ x2h, __nv_bfloat16* __restrict__ x2l,
    __nv_bfloat16* __restrict__ x3h, __nv_bfloat16* __restrict__ x3l)
{
    __shared__ float t[32][33];
    const int p  = blockIdx.x;
    const int c0 = blockIdx.y * 32;
    const int b  = blockIdx.z;
    const int tid = threadIdx.x;
    const int q   = tid & 31;
    const int ccb = tid >> 5;

    const float* src = y2 + (size_t)b * 128 * 4096;
    const int r0 = 2 * p - 1;
#pragma unroll
    for (int k = 0; k < 4; k++) {
        int cc = ccb + 8 * k;
        const float* row = src + (size_t)(c0 + cc) * 4096;
        float m = -CUDART_INF_F;
#pragma unroll
        for (int dr = 0; dr < 3; dr++) {
            int r = r0 + dr;
            if (r < 0 || r >= 64) continue;
#pragma unroll
            for (int dc = 0; dc < 3; dc++) {
                int col = 2 * q - 1 + dc;
                if (col < 0 || col >= 64) continue;
                m = fmaxf(m, row[r * 64 + col]);
            }
        }
        t[cc][q] = m;
    }
    __syncthreads();

    const int cc2 = tid & 31;
#pragma unroll
    for (int k = 0; k < 4; k++) {
        int q2 = ccb + 8 * k;
        __nv_bfloat16 h, l;
        split1(t[cc2][q2], h, l);
        size_t o2 = (size_t)b * 131072 + (size_t)(p * 32 + q2) * 128 + c0 + cc2;
        x2h[o2] = h; x2l[o2] = l;
        int c3 = 32 * (p & 3) + q2;
        int j3 = (c0 + cc2) * 8 + (p >> 2);
        size_t o3 = (size_t)b * 131072 + (size_t)c3 * 1024 + j3;
        x3h[o3] = h; x3l[o3] = l;
    }
}

// ---------------- transpose + bf16 split: NCHW [b][C][P] -> [b][p][c] ----------------
__global__ void transpose_split_kernel(const float* __restrict__ src_,
                                       __nv_bfloat16* __restrict__ oh, __nv_bfloat16* __restrict__ ol,
                                       int C, int P)
{
    __shared__ float t[32][33];
    int b = blockIdx.z;
    int p0 = blockIdx.x * 32, c0 = blockIdx.y * 32;
    int tx = threadIdx.x, ty = threadIdx.y;
    const float* src = src_ + (size_t)b * C * P;
#pragma unroll
    for (int k = 0; k < 4; k++)
        t[ty + 8 * k][tx] = src[(size_t)(c0 + ty + 8 * k) * P + p0 + tx];
    __syncthreads();
#pragma unroll
    for (int k = 0; k < 4; k++) {
        float v = t[tx][ty + 8 * k];
        __nv_bfloat16 h, l;
        split1(v, h, l);
        size_t o = (size_t)b * C * P + (size_t)(p0 + ty + 8 * k) * C + c0 + tx;
        oh[o] = h; ol[o] = l;
    }
}

#define CPITCH 72
#define CTILE (128 * CPITCH)

// ---------------- dual-output conv (validated R15) + ldmatrix B-frags ----------------
#define CDUAL_SMEM (8 * CTILE * 2)

__global__ __launch_bounds__(256) void conv_dual_kernel(
    const __nv_bfloat16* __restrict__ xth, const __nv_bfloat16* __restrict__ xtl,
    const float* __restrict__ W1, const float* __restrict__ bias1,
    const float* __restrict__ gam1, const float* __restrict__ beta1,
    const float* __restrict__ mean1, const float* __restrict__ var1,
    float* __restrict__ Y1, const float* __restrict__ resid1,
    const float* __restrict__ W2, const float* __restrict__ bias2,
    const float* __restrict__ gam2, const float* __restrict__ beta2,
    const float* __restrict__ mean2, const float* __restrict__ var2,
    float* __restrict__ Y2, const float* __restrict__ resid2,
    int K, int O)
{
    extern __shared__ __nv_bfloat16 cs[];
    __nv_bfloat16* W1h = cs;
    __nv_bfloat16* W1l = cs + CTILE;
    __nv_bfloat16* W2h = cs + 2 * CTILE;
    __nv_bfloat16* W2l = cs + 3 * CTILE;
    __nv_bfloat16* Bbuf[2][2] = {
        { cs + 4 * CTILE, cs + 5 * CTILE },
        { cs + 6 * CTILE, cs + 7 * CTILE } };

    const int HW = 4096;
    const int b  = blockIdx.z;
    const int p0 = blockIdx.x * 128;
    const int tid  = threadIdx.x;
    const int w    = tid >> 5;
    const int lane = tid & 31;
    const int grp  = lane >> 2;
    const int tig  = lane & 3;
    // ldmatrix lane addressing: group g=lane>>3, idx=lane&7
    const int rowoff = (((lane >> 3) >> 1) << 3) + (lane & 7);   // 0..15
    const int khalf  = ((lane >> 3) & 1) << 3;                   // 0 or 8 elems

    const __nv_bfloat16* srcH = xth + (size_t)b * HW * K + (size_t)p0 * K;
    const __nv_bfloat16* srcL = xtl + (size_t)b * HW * K + (size_t)p0 * K;
    const int nk = K >> 6;

    auto stage_B = [&](int kc, int bi) {
        uint32_t dh = smem_u32(Bbuf[bi][0]);
        uint32_t dl = smem_u32(Bbuf[bi][1]);
        int k0 = kc * 64;
#pragma unroll
        for (int l = 0; l < 4; l++) {
            int n = tid + l * 256;
            int r = n >> 3, q = n & 7;
            uint32_t off = (uint32_t)(r * (CPITCH * 2) + q * 16);
            CP_ASYNC16(dh + off, srcH + (size_t)r * K + k0 + q * 8);
            CP_ASYNC16(dl + off, srcL + (size_t)r * K + k0 + q * 8);
        }
    };

    float c1[16][4], c2[16][4];
#pragma unroll
    for (int nt = 0; nt < 16; nt++)
#pragma unroll
        for (int q = 0; q < 4; q++) { c1[nt][q] = 0.f; c2[nt][q] = 0.f; }

    stage_B(0, 0);
    CP_COMMIT();

    for (int kc = 0; kc < nk; kc++) {
        const int k0 = kc * 64;
        __syncthreads();
        if (kc + 1 < nk) stage_B(kc + 1, (kc + 1) & 1);
        CP_COMMIT();
#pragma unroll
        for (int l = 0; l < 16; l++) {
            int n = tid + l * 256;
            int o = n >> 5, kk = n & 31;
            float2 e1 = *(const float2*)(W1 + (size_t)o * K + k0 + 2 * kk);
            float2 e2 = *(const float2*)(W2 + (size_t)o * K + k0 + 2 * kk);
            uint32_t h, lo;
            split2(e1.x, e1.y, h, lo);
            *(uint32_t*)(W1h + o * CPITCH + 2 * kk) = h;
            *(uint32_t*)(W1l + o * CPITCH + 2 * kk) = lo;
            split2(e2.x, e2.y, h, lo);
            *(uint32_t*)(W2h + o * CPITCH + 2 * kk) = h;
            *(uint32_t*)(W2l + o * CPITCH + 2 * kk) = lo;
        }
        CP_WAIT1();
        __syncthreads();

        const uint32_t aBh = smem_u32(Bbuf[kc & 1][0]);
        const uint32_t aBl = smem_u32(Bbuf[kc & 1][1]);
#pragma unroll
        for (int kt = 0; kt < 4; kt++) {
            const int wo = (w * 16 + grp) * CPITCH + kt * 16 + 2 * tig;
            uint32_t a1h0 = *(const uint32_t*)(W1h + wo);
            uint32_t a1h1 = *(const uint32_t*)(W1h + wo + 8 * CPITCH);
            uint32_t a1h2 = *(const uint32_t*)(W1h + wo + 8);
            uint32_t a1h3 = *(const uint32_t*)(W1h + wo + 8 * CPITCH + 8);
            uint32_t a1l0 = *(const uint32_t*)(W1l + wo);
            uint32_t a1l1 = *(const uint32_t*)(W1l + wo + 8 * CPITCH);
            uint32_t a1l2 = *(const uint32_t*)(W1l + wo + 8);
            uint32_t a1l3 = *(const uint32_t*)(W1l + wo + 8 * CPITCH + 8);
            uint32_t a2h0 = *(const uint32_t*)(W2h + wo);
            uint32_t a2h1 = *(const uint32_t*)(W2h + wo + 8 * CPITCH);
            uint32_t a2h2 = *(const uint32_t*)(W2h + wo + 8);
            uint32_t a2h3 = *(const uint32_t*)(W2h + wo + 8 * CPITCH + 8);
            uint32_t a2l0 = *(const uint32_t*)(W2l + wo);
            uint32_t a2l1 = *(const uint32_t*)(W2l + wo + 8 * CPITCH);
            uint32_t a2l2 = *(const uint32_t*)(W2l + wo + 8);
            uint32_t a2l3 = *(const uint32_t*)(W2l + wo + 8 * CPITCH + 8);
#pragma unroll
            for (int np = 0; np < 8; np++) {
                uint32_t off = (uint32_t)(((np * 16 + rowoff) * CPITCH + kt * 16 + khalf) * 2);
                uint32_t h0, h1, h2, h3, q0, q1, q2, q3;
                ldsm4(h0, h1, h2, h3, aBh + off);
                ldsm4(q0, q1, q2, q3, aBl + off);
                int n0 = 2 * np, n1 = 2 * np + 1;
                mma_bf16(c1[n0][0], c1[n0][1], c1[n0][2], c1[n0][3], a1h0, a1h1, a1h2, a1h3, h0, h1);
                mma_bf16(c1[n0][0], c1[n0][1], c1[n0][2], c1[n0][3], a1h0, a1h1, a1h2, a1h3, q0, q1);
                mma_bf16(c1[n0][0], c1[n0][1], c1[n0][2], c1[n0][3], a1l0, a1l1, a1l2, a1l3, h0, h1);
                mma_bf16(c2[n0][0], c2[n0][1], c2[n0][2], c2[n0][3], a2h0, a2h1, a2h2, a2h3, h0, h1);
                mma_bf16(c2[n0][0], c2[n0][1], c2[n0][2], c2[n0][3], a2h0, a2h1, a2h2, a2h3, q0, q1);
                mma_bf16(c2[n0][0], c2[n0][1], c2[n0][2], c2[n0][3], a2l0, a2l1, a2l2, a2l3, h0, h1);
                mma_bf16(c1[n1][0], c1[n1][1], c1[n1][2], c1[n1][3], a1h0, a1h1, a1h2, a1h3, h2, h3);
                mma_bf16(c1[n1][0], c1[n1][1], c1[n1][2], c1[n1][3], a1h0, a1h1, a1h2, a1h3, q2, q3);
                mma_bf16(c1[n1][0], c1[n1][1], c1[n1][2], c1[n1][3], a1l0, a1l1, a1l2, a1l3, h2, h3);
                mma_bf16(c2[n1][0], c2[n1][1], c2[n1][2], c2[n1][3], a2h0, a2h1, a2h2, a2h3, h2, h3);
                mma_bf16(c2[n1][0], c2[n1][1], c2[n1][2], c2[n1][3], a2h0, a2h1, a2h2, a2h3, q2, q3);
                mma_bf16(c2[n1][0], c2[n1][1], c2[n1][2], c2[n1][3], a2l0, a2l1, a2l2, a2l3, h2, h3);
            }
        }
    }

    const int o_r0 = w * 16 + grp;
    const int o_r1 = o_r0 + 8;
#pragma unroll
    for (int sel = 0; sel < 2; sel++) {
        const float* bias = sel ? bias2 : bias1;
        const float* gam  = sel ? gam2 : gam1;
        const float* beta = sel ? beta2 : beta1;
        const float* mean = sel ? mean2 : mean1;
        const float* var  = sel ? var2 : var1;
        float* Y          = sel ? Y2 : Y1;
        const float* rsd  = sel ? resid2 : resid1;
        float (*cc)[4]    = sel ? c2 : c1;
        float s0  = gam[o_r0] * rsqrtf(var[o_r0] + EPS);
        float sh0 = beta[o_r0] - mean[o_r0] * s0;
        float bi0 = bias[o_r0];
        float s1  = gam[o_r1] * rsqrtf(var[o_r1] + EPS);
        float sh1 = beta[o_r1] - mean[o_r1] * s1;
        float bi1 = bias[o_r1];
        float* y0 = Y + (size_t)b * O * HW + (size_t)o_r0 * HW + p0;
        float* y1 = Y + (size_t)b * O * HW + (size_t)o_r1 * HW + p0;
        const float* rs0 = rsd ? rsd + (size_t)b * O * HW + (size_t)o_r0 * HW + p0 : nullptr;
        const float* rs1 = rsd ? rsd + (size_t)b * O * HW + (size_t)o_r1 * HW + p0 : nullptr;
#pragma unroll
        for (int nt = 0; nt < 16; nt++) {
            int p = nt * 8 + 2 * tig;
            float v00 = fmaxf((cc[nt][0] + bi0) * s0 + sh0, 0.f);
            float v01 = fmaxf((cc[nt][1] + bi0) * s0 + sh0, 0.f);
            float v10 = fmaxf((cc[nt][2] + bi1) * s1 + sh1, 0.f);
            float v11 = fmaxf((cc[nt][3] + bi1) * s1 + sh1, 0.f);
            if (rs0) {
                float2 r0v = *(const float2*)(rs0 + p);
                float2 r1v = *(const float2*)(rs1 + p);
                v00 += r0v.x; v01 += r0v.y; v10 += r1v.x; v11 += r1v.y;
            }
            *(float2*)(y0 + p) = make_float2(v00, v01);
            *(float2*)(y1 + p) = make_float2(v10, v11);
        }
    }
}

// ---------------- attention: R15 structure + ldmatrix B-frags ----------------
#define B1PITCH 136
#define B2PITCH 72
#define B1ELEMS (64 * B1PITCH)
#define B2ELEMS (128 * B2PITCH)
#define STG_ELEMS (2 * B1ELEMS + 2 * B2ELEMS)
#define ATTN_SMEM (3 * STG_ELEMS * 2)

__global__ __launch_bounds__(256) void attn_mma_kernel(
    const float* __restrict__ x1,
    const __nv_bfloat16* __restrict__ x2h, const __nv_bfloat16* __restrict__ x2l,
    const __nv_bfloat16* __restrict__ x3h, const __nv_bfloat16* __restrict__ x3l,
    float* __restrict__ out)
{
    extern __shared__ __nv_bfloat16 smb[];

    const int tid  = threadIdx.x;
    const int w    = tid >> 5;
    const int lane = tid & 31;
    const int grp  = lane >> 2;
    const int tig  = lane & 3;
    const int b    = blockIdx.y;
    const int i0   = blockIdx.x * 128;
    const int r0   = w * 16 + grp;
    const int rowoff = (((lane >> 3) >> 1) << 3) + (lane & 7);
    const int khalf  = ((lane >> 3) & 1) << 3;

    uint32_t ahi[8][4], alo[8][4];
    {
        const float* a0p = x1 + (size_t)b * 524288 + (size_t)(i0 + r0) * 128;
        const float* a1p = a0p + 8 * 128;
#pragma unroll
        for (int kt = 0; kt < 8; kt++) {
            float2 e00 = *(const float2*)(a0p + kt * 16 + 2 * tig);
            float2 e01 = *(const float2*)(a0p + kt * 16 + 2 * tig + 8);
            float2 e10 = *(const float2*)(a1p + kt * 16 + 2 * tig);
            float2 e11 = *(const float2*)(a1p + kt * 16 + 2 * tig + 8);
            split2(e00.x, e00.y, ahi[kt][0], alo[kt][0]);
            split2(e10.x, e10.y, ahi[kt][1], alo[kt][1]);
            split2(e01.x, e01.y, ahi[kt][2], alo[kt][2]);
            split2(e11.x, e11.y, ahi[kt][3], alo[kt][3]);
        }
    }

    const __nv_bfloat16* X2Hb = x2h + (size_t)b * 131072;
    const __nv_bfloat16* X2Lb = x2l + (size_t)b * 131072;
    const __nv_bfloat16* X3Hb = x3h + (size_t)b * 131072;
    const __nv_bfloat16* X3Lb = x3l + (size_t)b * 131072;

    const uint32_t smbase = smem_u32(smb);

    auto stage = [&](int ch) {
        const int st = ch % 3;
        const uint32_t s0  = smbase + (uint32_t)st * (STG_ELEMS * 2);
        const uint32_t b1h = s0;
        const uint32_t b1l = s0 + B1ELEMS * 2;
        const uint32_t b2h = s0 + 2 * B1ELEMS * 2;
        const uint32_t b2l = b2h + B2ELEMS * 2;
        const int j0 = ch * 64;
#pragma unroll
        for (int l = 0; l < 4; l++) {
            int n = tid + l * 256;
            {
                int r = n >> 4, p = n & 15;
                uint32_t off = (uint32_t)(r * (B1PITCH * 2) + p * 16);
                CP_ASYNC16(b1h + off, X2Hb + (size_t)(j0 + r) * 128 + p * 8);
                CP_ASYNC16(b1l + off, X2Lb + (size_t)(j0 + r) * 128 + p * 8);
            }
            {
                int r = n >> 3, p = n & 7;
                uint32_t off = (uint32_t)(r * (B2PITCH * 2) + p * 16);
                CP_ASYNC16(b2h + off, X3Hb + (size_t)r * 1024 + j0 + p * 8);
                CP_ASYNC16(b2l + off, X3Lb + (size_t)r * 1024 + j0 + p * 8);
            }
        }
    };

    float o[16][4];
#pragma unroll
    for (int nt = 0; nt < 16; nt++)
#pragma unroll
        for (int q = 0; q < 4; q++) o[nt][q] = 0.f;
    float m0 = -CUDART_INF_F, m1 = -CUDART_INF_F, l0 = 0.f, l1 = 0.f;

    stage(0); CP_COMMIT();
    stage(1); CP_COMMIT();

    for (int ch = 0; ch < 16; ch++) {
        CP_WAIT1();
        __syncthreads();

        const uint32_t sbase = smbase + (uint32_t)(ch % 3) * (STG_ELEMS * 2);
        const uint32_t aB1H = sbase;
        const uint32_t aB1L = sbase + B1ELEMS * 2;
        const uint32_t aB2H = sbase + 2 * B1ELEMS * 2;
        const uint32_t aB2L = aB2H + B2ELEMS * 2;

        // ---- gemm1: s[i 16][j 64] ----
        float s[8][4];
#pragma unroll
        for (int nt = 0; nt < 8; nt++)
#pragma unroll
            for (int q = 0; q < 4; q++) s[nt][q] = 0.f;

#pragma unroll
        for (int kt = 0; kt < 8; kt++) {
#pragma unroll
            for (int np = 0; np < 4; np++) {
                uint32_t off = (uint32_t)(((np * 16 + rowoff) * B1PITCH + kt * 16 + khalf) * 2);
                uint32_t h0, h1, h2, h3, q0, q1, q2, q3;
                ldsm4(h0, h1, h2, h3, aB1H + off);
                ldsm4(q0, q1, q2, q3, aB1L + off);
                int n0 = 2 * np, n1 = 2 * np + 1;
                mma_bf16(s[n0][0], s[n0][1], s[n0][2], s[n0][3],
                         ahi[kt][0], ahi[kt][1], ahi[kt][2], ahi[kt][3], h0, h1);
                mma_bf16(s[n0][0], s[n0][1], s[n0][2], s[n0][3],
                         ahi[kt][0], ahi[kt][1], ahi[kt][2], ahi[kt][3], q0, q1);
                mma_bf16(s[n0][0], s[n0][1], s[n0][2], s[n0][3],
                         alo[kt][0], alo[kt][1], alo[kt][2], alo[kt][3], h0, h1);
                mma_bf16(s[n1][0], s[n1][1], s[n1][2], s[n1][3],
                         ahi[kt][0], ahi[kt][1], ahi[kt][2], ahi[kt][3], h2, h3);
                mma_bf16(s[n1][0], s[n1][1], s[n1][2], s[n1][3],
                         ahi[kt][0], ahi[kt][1], ahi[kt][2], ahi[kt][3], q2, q3);
                mma_bf16(s[n1][0], s[n1][1], s[n1][2], s[n1][3],
                         alo[kt][0], alo[kt][1], alo[kt][2], alo[kt][3], h2, h3);
            }
        }

        // ---- online softmax ----
        float mx0 = s[0][0], mx1 = s[0][2];
#pragma unroll
        for (int nt = 0; nt < 8; nt++) {
            mx0 = fmaxf(mx0, fmaxf(s[nt][0], s[nt][1]));
            mx1 = fmaxf(mx1, fmaxf(s[nt][2], s[nt][3]));
        }
        mx0 = fmaxf(mx0, __shfl_xor_sync(0xffffffffu, mx0, 1));
        mx0 = fmaxf(mx0, __shfl_xor_sync(0xffffffffu, mx0, 2));
        mx1 = fmaxf(mx1, __shfl_xor_sync(0xffffffffu, mx1, 1));
        mx1 = fmaxf(mx1, __shfl_xor_sync(0xffffffffu, mx1, 2));
        float n0 = fmaxf(m0, mx0), n1 = fmaxf(m1, mx1);
        float f0 = __expf(m0 - n0), f1 = __expf(m1 - n1);
        m0 = n0; m1 = n1;
        float ps0 = 0.f, ps1 = 0.f;
#pragma unroll
        for (int nt = 0; nt < 8; nt++) {
            s[nt][0] = __expf(s[nt][0] - n0);
            s[nt][1] = __expf(s[nt][1] - n0);
            s[nt][2] = __expf(s[nt][2] - n1);
            s[nt][3] = __expf(s[nt][3] - n1);
            ps0 += s[nt][0] + s[nt][1];
            ps1 += s[nt][2] + s[nt][3];
        }
        ps0 += __shfl_xor_sync(0xffffffffu, ps0, 1);
        ps0 += __shfl_xor_sync(0xffffffffu, ps0, 2);
        ps1 += __shfl_xor_sync(0xffffffffu, ps1, 1);
        ps1 += __shfl_xor_sync(0xffffffffu, ps1, 2);
        l0 = l0 * f0 + ps0;
        l1 = l1 * f1 + ps1;
#pragma unroll
        for (int nt = 0; nt < 16; nt++) {
            o[nt][0] *= f0; o[nt][1] *= f0;
            o[nt][2] *= f1; o[nt][3] *= f1;
        }

        uint32_t phi[4][4], plo[4][4];
#pragma unroll
        for (int kt = 0; kt < 4; kt++) {
            split2(s[2 * kt][0],     s[2 * kt][1],     phi[kt][0], plo[kt][0]);
            split2(s[2 * kt][2],     s[2 * kt][3],     phi[kt][1], plo[kt][1]);
            split2(s[2 * kt + 1][0], s[2 * kt + 1][1], phi[kt][2], plo[kt][2]);
            split2(s[2 * kt + 1][2], s[2 * kt + 1][3], phi[kt][3], plo[kt][3]);
        }

        // ---- gemm2 ----
#pragma unroll
        for (int kt = 0; kt < 4; kt++) {
#pragma unroll
            for (int np = 0; np < 8; np++) {
                uint32_t off = (uint32_t)(((np * 16 + rowoff) * B2PITCH + kt * 16 + khalf) * 2);
                uint32_t h0, h1, h2, h3, q0, q1, q2, q3;
                ldsm4(h0, h1, h2, h3, aB2H + off);
                ldsm4(q0, q1, q2, q3, aB2L + off);
                int n0 = 2 * np, n1 = 2 * np + 1;
                mma_bf16(o[n0][0], o[n0][1], o[n0][2], o[n0][3],
                         phi[kt][0], phi[kt][1], phi[kt][2], phi[kt][3], h0, h1);
                mma_bf16(o[n0][0], o[n0][1], o[n0][2], o[n0][3],
                         phi[kt][0], phi[kt][1], phi[kt][2], phi[kt][3], q0, q1);
                mma_bf16(o[n0][0], o[n0][1], o[n0][2], o[n0][3],
                         plo[kt][0], plo[kt][1], plo[kt][2], plo[kt][3], h0, h1);
                mma_bf16(o[n1][0], o[n1][1], o[n1][2], o[n1][3],
                         phi[kt][0], phi[kt][1], phi[kt][2], phi[kt][3], h2, h3);
                mma_bf16(o[n1][0], o[n1][1], o[n1][2], o[n1][3],
                         phi[kt][0], phi[kt][1], phi[kt][2], phi[kt][3], q2, q3);
                mma_bf16(o[n1][0], o[n1][1], o[n1][2], o[n1][3],
                         plo[kt][0], plo[kt][1], plo[kt][2], plo[kt][3], h2, h3);
            }
        }

        if (ch + 2 < 16) stage(ch + 2);
        CP_COMMIT();
    }

    float inv0 = 1.0f / l0, inv1 = 1.0f / l1;
    float* og0 = out + (size_t)b * 524288 + (size_t)(i0 + r0) * 128;
    float* og1 = og0 + 8 * 128;
#pragma unroll
    for (int nt = 0; nt < 16; nt++) {
        *(float2*)(og0 + nt * 8 + 2 * tig) = make_float2(o[nt][0] * inv0, o[nt][1] * inv0);
        *(float2*)(og1 + nt * 8 + 2 * tig) = make_float2(o[nt][2] * inv1, o[nt][3] * inv1);
    }
}

// ---------------- launcher ----------------
extern "C" void kernel_launch(void* const* d_in, const int* in_sizes, int n_in,
                              void* d_out, int out_size)
{
    const float* a       = (const float*)d_in[0];
    const float* conv1_w = (const float*)d_in[1];
    const float* conv1_b = (const float*)d_in[2];
    const float* bn1_g   = (const float*)d_in[3];
    const float* bn1_b   = (const float*)d_in[4];
    const float* bn1_m   = (const float*)d_in[5];
    const float* bn1_v   = (const float*)d_in[6];
    const float* conv2_w = (const float*)d_in[7];
    const float* conv2_b = (const float*)d_in[8];
    const float* bn2_g   = (const float*)d_in[9];
    const float* bn2_b   = (const float*)d_in[10];
    const float* bn2_m   = (const float*)d_in[11];
    const float* bn2_v   = (const float*)d_in[12];
    const float* conv3_w = (const float*)d_in[13];
    const float* conv3_b = (const float*)d_in[14];
    const float* bn3_g   = (const float*)d_in[15];
    const float* bn3_b   = (const float*)d_in[16];
    const float* bn3_m   = (const float*)d_in[17];
    const float* bn3_v   = (const float*)d_in[18];
    float* out = (float*)d_out;

    float *p_x1, *p_y2, *p_attn;
    __nv_bfloat16 *p_x2h, *p_x2l, *p_x3h, *p_x3l, *p_ath, *p_atl;
    cudaGetSymbolAddress((void**)&p_x1,   g_x1);
    cudaGetSymbolAddress((void**)&p_y2,   g_y2);
    cudaGetSymbolAddress((void**)&p_attn, g_attn);
    cudaGetSymbolAddress((void**)&p_x2h,  g_x2t_hi);
    cudaGetSymbolAddress((void**)&p_x2l,  g_x2t_lo);
    cudaGetSymbolAddress((void**)&p_x3h,  g_x3t_hi);
    cudaGetSymbolAddress((void**)&p_x3l,  g_x3t_lo);
    cudaGetSymbolAddress((void**)&p_ath,  g_at_hi);
    cudaGetSymbolAddress((void**)&p_atl,  g_at_lo);

    cudaFuncSetAttribute(attn_mma_kernel,  cudaFuncAttributeMaxDynamicSharedMemorySize, ATTN_SMEM);
    cudaFuncSetAttribute(conv_dual_kernel, cudaFuncAttributeMaxDynamicSharedMemorySize, CDUAL_SMEM);

    dim3 blk(256);

    transpose_split_kernel<<<dim3(128, 8, 8), dim3(32, 8)>>>(a, p_ath, p_atl, 256, 4096);

    conv_dual_kernel<<<dim3(32, 1, 8), blk, CDUAL_SMEM>>>(
        p_ath, p_atl,
        conv1_w, conv1_b, bn1_g, bn1_b, bn1_m, bn1_v, p_x1, nullptr,
        conv2_w, conv2_b, bn2_g, bn2_b, bn2_m, bn2_v, p_y2, nullptr,
        256, 128);

    pool_split_kernel<<<dim3(32, 4, 8), blk>>>(p_y2, p_x2h, p_x2l, p_x3h, p_x3l);

    attn_mma_kernel<<<dim3(32, 8), blk, ATTN_SMEM>>>(
        p_x1, p_x2h, p_x2l, p_x3h, p_x3l, p_attn);

    transpose_split_kernel<<<dim3(128, 4, 8), dim3(32, 8)>>>(p_attn, p_ath, p_atl, 128, 4096);

    conv_dual_kernel<<<dim3(32, 1, 8), blk, CDUAL_SMEM>>>(
        p_ath, p_atl,
        conv3_w,             conv3_b,       bn3_g,       bn3_b,       bn3_m,       bn3_v,
        out,                 a,
        conv3_w + 128 * 128, conv3_b + 128, bn3_g + 128, bn3_b + 128, bn3_m + 128, bn3_v + 128,
        out + 128 * 4096,    a + 128 * 4096,
        128, 256);
}

// round 17
// speedup vs baseline: 1.4188x; 1.0672x over previous
#include <cuda_runtime.h>
#include <cuda_bf16.h>
#include <math_constants.h>
#include <cstdint>

#define EPS 1e-5f

// ---------------- scratch ----------------
__device__ float g_x1[8 * 128 * 4096];
__device__ float g_y2[8 * 128 * 4096];
__device__ float g_attn[8 * 128 * 4096];
__device__ __nv_bfloat16 g_x2t_hi[8 * 1024 * 128];
__device__ __nv_bfloat16 g_x2t_lo[8 * 1024 * 128];
__device__ __nv_bfloat16 g_x3t_hi[8 * 128 * 1024];
__device__ __nv_bfloat16 g_x3t_lo[8 * 128 * 1024];
__device__ __nv_bfloat16 g_at_hi[8 * 4096 * 256];
__device__ __nv_bfloat16 g_at_lo[8 * 4096 * 256];

// ---------------- helpers ----------------
__device__ __forceinline__ void mma_bf16(float& c0, float& c1, float& c2, float& c3,
                                         uint32_t a0, uint32_t a1, uint32_t a2, uint32_t a3,
                                         uint32_t b0, uint32_t b1)
{
    asm volatile("mma.sync.aligned.m16n8k16.row.col.f32.bf16.bf16.f32 "
                 "{%0,%1,%2,%3}, {%4,%5,%6,%7}, {%8,%9}, {%0,%1,%2,%3};"
                 : "+f"(c0), "+f"(c1), "+f"(c2), "+f"(c3)
                 : "r"(a0), "r"(a1), "r"(a2), "r"(a3), "r"(b0), "r"(b1));
}
__device__ __forceinline__ void ldsm4(uint32_t& r0, uint32_t& r1, uint32_t& r2, uint32_t& r3,
                                      uint32_t addr)
{
    asm volatile("ldmatrix.sync.aligned.m8n8.x4.shared.b16 {%0,%1,%2,%3}, [%4];"
                 : "=r"(r0), "=r"(r1), "=r"(r2), "=r"(r3) : "r"(addr));
}
__device__ __forceinline__ void split2(float e0, float e1, uint32_t& hi, uint32_t& lo)
{
    asm("cvt.rn.bf16x2.f32 %0, %1, %2;" : "=r"(hi) : "f"(e1), "f"(e0));
    float f0h = __uint_as_float(hi << 16);
    float f1h = __uint_as_float(hi & 0xffff0000u);
    asm("cvt.rn.bf16x2.f32 %0, %1, %2;" : "=r"(lo) : "f"(e1 - f1h), "f"(e0 - f0h));
}
__device__ __forceinline__ uint32_t pack_bf16x2(float e0, float e1)
{
    uint32_t r;
    asm("cvt.rn.bf16x2.f32 %0, %1, %2;" : "=r"(r) : "f"(e1), "f"(e0));
    return r;
}
__device__ __forceinline__ void split1(float v, __nv_bfloat16& h, __nv_bfloat16& l)
{
    h = __float2bfloat16(v);
    l = __float2bfloat16(v - __bfloat162float(h));
}
__device__ __forceinline__ uint32_t smem_u32(const void* p) {
    uint32_t a;
    asm("{ .reg .u64 t; cvta.to.shared.u64 t, %1; cvt.u32.u64 %0, t; }" : "=r"(a) : "l"(p));
    return a;
}
#define CP_ASYNC16(dst, src) asm volatile("cp.async.cg.shared.global [%0], [%1], 16;" :: "r"(dst), "l"(src))
#define CP_COMMIT()          asm volatile("cp.async.commit_group;" ::: "memory")
#define CP_WAIT1()           asm volatile("cp.async.wait_group 1;" ::: "memory")

// ---------------- fused maxpool + attention operand layouts (validated R8) ----------------
__global__ __launch_bounds__(256) void pool_split_kernel(
    const float* __restrict__ y2,
    __nv_bfloat16* __restrict__ x2h, __nv_bfloat16* __restrict__ x2l,
    __nv_bfloat16* __restrict__ x3h, __nv_bfloat16* __restrict__ x3l)
{
    __shared__ float t[32][33];
    const int p  = blockIdx.x;
    const int c0 = blockIdx.y * 32;
    const int b  = blockIdx.z;
    const int tid = threadIdx.x;
    const int q   = tid & 31;
    const int ccb = tid >> 5;

    const float* src = y2 + (size_t)b * 128 * 4096;
    const int r0 = 2 * p - 1;
#pragma unroll
    for (int k = 0; k < 4; k++) {
        int cc = ccb + 8 * k;
        const float* row = src + (size_t)(c0 + cc) * 4096;
        float m = -CUDART_INF_F;
#pragma unroll
        for (int dr = 0; dr < 3; dr++) {
            int r = r0 + dr;
            if (r < 0 || r >= 64) continue;
#pragma unroll
            for (int dc = 0; dc < 3; dc++) {
                int col = 2 * q - 1 + dc;
                if (col < 0 || col >= 64) continue;
                m = fmaxf(m, row[r * 64 + col]);
            }
        }
        t[cc][q] = m;
    }
    __syncthreads();

    const int cc2 = tid & 31;
#pragma unroll
    for (int k = 0; k < 4; k++) {
        int q2 = ccb + 8 * k;
        __nv_bfloat16 h, l;
        split1(t[cc2][q2], h, l);
        size_t o2 = (size_t)b * 131072 + (size_t)(p * 32 + q2) * 128 + c0 + cc2;
        x2h[o2] = h; x2l[o2] = l;
        int c3 = 32 * (p & 3) + q2;
        int j3 = (c0 + cc2) * 8 + (p >> 2);
        size_t o3 = (size_t)b * 131072 + (size_t)c3 * 1024 + j3;
        x3h[o3] = h; x3l[o3] = l;
    }
}

// ---------------- transpose + bf16 split: NCHW [b][C][P] -> [b][p][c] ----------------
__global__ void transpose_split_kernel(const float* __restrict__ src_,
                                       __nv_bfloat16* __restrict__ oh, __nv_bfloat16* __restrict__ ol,
                                       int C, int P)
{
    __shared__ float t[32][33];
    int b = blockIdx.z;
    int p0 = blockIdx.x * 32, c0 = blockIdx.y * 32;
    int tx = threadIdx.x, ty = threadIdx.y;
    const float* src = src_ + (size_t)b * C * P;
#pragma unroll
    for (int k = 0; k < 4; k++)
        t[ty + 8 * k][tx] = src[(size_t)(c0 + ty + 8 * k) * P + p0 + tx];
    __syncthreads();
#pragma unroll
    for (int k = 0; k < 4; k++) {
        float v = t[tx][ty + 8 * k];
        __nv_bfloat16 h, l;
        split1(v, h, l);
        size_t o = (size_t)b * C * P + (size_t)(p0 + ty + 8 * k) * C + c0 + tx;
        oh[o] = h; ol[o] = l;
    }
}

#define CPITCH 72
#define CTILE (128 * CPITCH)

// ---------------- dual-output conv (validated R15/R16) ----------------
#define CDUAL_SMEM (8 * CTILE * 2)

__global__ __launch_bounds__(256) void conv_dual_kernel(
    const __nv_bfloat16* __restrict__ xth, const __nv_bfloat16* __restrict__ xtl,
    const float* __restrict__ W1, const float* __restrict__ bias1,
    const float* __restrict__ gam1, const float* __restrict__ beta1,
    const float* __restrict__ mean1, const float* __restrict__ var1,
    float* __restrict__ Y1, const float* __restrict__ resid1,
    const float* __restrict__ W2, const float* __restrict__ bias2,
    const float* __restrict__ gam2, const float* __restrict__ beta2,
    const float* __restrict__ mean2, const float* __restrict__ var2,
    float* __restrict__ Y2, const float* __restrict__ resid2,
    int K, int O)
{
    extern __shared__ __nv_bfloat16 cs[];
    __nv_bfloat16* W1h = cs;
    __nv_bfloat16* W1l = cs + CTILE;
    __nv_bfloat16* W2h = cs + 2 * CTILE;
    __nv_bfloat16* W2l = cs + 3 * CTILE;
    __nv_bfloat16* Bbuf[2][2] = {
        { cs + 4 * CTILE, cs + 5 * CTILE },
        { cs + 6 * CTILE, cs + 7 * CTILE } };

    const int HW = 4096;
    const int b  = blockIdx.z;
    const int p0 = blockIdx.x * 128;
    const int tid  = threadIdx.x;
    const int w    = tid >> 5;
    const int lane = tid & 31;
    const int grp  = lane >> 2;
    const int tig  = lane & 3;
    const int rowoff = (((lane >> 3) >> 1) << 3) + (lane & 7);
    const int khalf  = ((lane >> 3) & 1) << 3;

    const __nv_bfloat16* srcH = xth + (size_t)b * HW * K + (size_t)p0 * K;
    const __nv_bfloat16* srcL = xtl + (size_t)b * HW * K + (size_t)p0 * K;
    const int nk = K >> 6;

    auto stage_B = [&](int kc, int bi) {
        uint32_t dh = smem_u32(Bbuf[bi][0]);
        uint32_t dl = smem_u32(Bbuf[bi][1]);
        int k0 = kc * 64;
#pragma unroll
        for (int l = 0; l < 4; l++) {
            int n = tid + l * 256;
            int r = n >> 3, q = n & 7;
            uint32_t off = (uint32_t)(r * (CPITCH * 2) + q * 16);
            CP_ASYNC16(dh + off, srcH + (size_t)r * K + k0 + q * 8);
            CP_ASYNC16(dl + off, srcL + (size_t)r * K + k0 + q * 8);
        }
    };

    float c1[16][4], c2[16][4];
#pragma unroll
    for (int nt = 0; nt < 16; nt++)
#pragma unroll
        for (int q = 0; q < 4; q++) { c1[nt][q] = 0.f; c2[nt][q] = 0.f; }

    stage_B(0, 0);
    CP_COMMIT();

    for (int kc = 0; kc < nk; kc++) {
        const int k0 = kc * 64;
        __syncthreads();
        if (kc + 1 < nk) stage_B(kc + 1, (kc + 1) & 1);
        CP_COMMIT();
#pragma unroll
        for (int l = 0; l < 16; l++) {
            int n = tid + l * 256;
            int o = n >> 5, kk = n & 31;
            float2 e1 = *(const float2*)(W1 + (size_t)o * K + k0 + 2 * kk);
            float2 e2 = *(const float2*)(W2 + (size_t)o * K + k0 + 2 * kk);
            uint32_t h, lo;
            split2(e1.x, e1.y, h, lo);
            *(uint32_t*)(W1h + o * CPITCH + 2 * kk) = h;
            *(uint32_t*)(W1l + o * CPITCH + 2 * kk) = lo;
            split2(e2.x, e2.y, h, lo);
            *(uint32_t*)(W2h + o * CPITCH + 2 * kk) = h;
            *(uint32_t*)(W2l + o * CPITCH + 2 * kk) = lo;
        }
        CP_WAIT1();
        __syncthreads();

        const uint32_t aBh = smem_u32(Bbuf[kc & 1][0]);
        const uint32_t aBl = smem_u32(Bbuf[kc & 1][1]);
#pragma unroll
        for (int kt = 0; kt < 4; kt++) {
            const int wo = (w * 16 + grp) * CPITCH + kt * 16 + 2 * tig;
            uint32_t a1h0 = *(const uint32_t*)(W1h + wo);
            uint32_t a1h1 = *(const uint32_t*)(W1h + wo + 8 * CPITCH);
            uint32_t a1h2 = *(const uint32_t*)(W1h + wo + 8);
            uint32_t a1h3 = *(const uint32_t*)(W1h + wo + 8 * CPITCH + 8);
            uint32_t a1l0 = *(const uint32_t*)(W1l + wo);
            uint32_t a1l1 = *(const uint32_t*)(W1l + wo + 8 * CPITCH);
            uint32_t a1l2 = *(const uint32_t*)(W1l + wo + 8);
            uint32_t a1l3 = *(const uint32_t*)(W1l + wo + 8 * CPITCH + 8);
            uint32_t a2h0 = *(const uint32_t*)(W2h + wo);
            uint32_t a2h1 = *(const uint32_t*)(W2h + wo + 8 * CPITCH);
            uint32_t a2h2 = *(const uint32_t*)(W2h + wo + 8);
            uint32_t a2h3 = *(const uint32_t*)(W2h + wo + 8 * CPITCH + 8);
            uint32_t a2l0 = *(const uint32_t*)(W2l + wo);
            uint32_t a2l1 = *(const uint32_t*)(W2l + wo + 8 * CPITCH);
            uint32_t a2l2 = *(const uint32_t*)(W2l + wo + 8);
            uint32_t a2l3 = *(const uint32_t*)(W2l + wo + 8 * CPITCH + 8);
#pragma unroll
            for (int np = 0; np < 8; np++) {
                uint32_t off = (uint32_t)(((np * 16 + rowoff) * CPITCH + kt * 16 + khalf) * 2);
                uint32_t h0, h1, h2, h3, q0, q1, q2, q3;
                ldsm4(h0, h1, h2, h3, aBh + off);
                ldsm4(q0, q1, q2, q3, aBl + off);
                int n0 = 2 * np, n1 = 2 * np + 1;
                mma_bf16(c1[n0][0], c1[n0][1], c1[n0][2], c1[n0][3], a1h0, a1h1, a1h2, a1h3, h0, h1);
                mma_bf16(c1[n0][0], c1[n0][1], c1[n0][2], c1[n0][3], a1h0, a1h1, a1h2, a1h3, q0, q1);
                mma_bf16(c1[n0][0], c1[n0][1], c1[n0][2], c1[n0][3], a1l0, a1l1, a1l2, a1l3, h0, h1);
                mma_bf16(c2[n0][0], c2[n0][1], c2[n0][2], c2[n0][3], a2h0, a2h1, a2h2, a2h3, h0, h1);
                mma_bf16(c2[n0][0], c2[n0][1], c2[n0][2], c2[n0][3], a2h0, a2h1, a2h2, a2h3, q0, q1);
                mma_bf16(c2[n0][0], c2[n0][1], c2[n0][2], c2[n0][3], a2l0, a2l1, a2l2, a2l3, h0, h1);
                mma_bf16(c1[n1][0], c1[n1][1], c1[n1][2], c1[n1][3], a1h0, a1h1, a1h2, a1h3, h2, h3);
                mma_bf16(c1[n1][0], c1[n1][1], c1[n1][2], c1[n1][3], a1h0, a1h1, a1h2, a1h3, q2, q3);
                mma_bf16(c1[n1][0], c1[n1][1], c1[n1][2], c1[n1][3], a1l0, a1l1, a1l2, a1l3, h2, h3);
                mma_bf16(c2[n1][0], c2[n1][1], c2[n1][2], c2[n1][3], a2h0, a2h1, a2h2, a2h3, h2, h3);
                mma_bf16(c2[n1][0], c2[n1][1], c2[n1][2], c2[n1][3], a2h0, a2h1, a2h2, a2h3, q2, q3);
                mma_bf16(c2[n1][0], c2[n1][1], c2[n1][2], c2[n1][3], a2l0, a2l1, a2l2, a2l3, h2, h3);
            }
        }
    }

    const int o_r0 = w * 16 + grp;
    const int o_r1 = o_r0 + 8;
#pragma unroll
    for (int sel = 0; sel < 2; sel++) {
        const float* bias = sel ? bias2 : bias1;
        const float* gam  = sel ? gam2 : gam1;
        const float* beta = sel ? beta2 : beta1;
        const float* mean = sel ? mean2 : mean1;
        const float* var  = sel ? var2 : var1;
        float* Y          = sel ? Y2 : Y1;
        const float* rsd  = sel ? resid2 : resid1;
        float (*cc)[4]    = sel ? c2 : c1;
        float s0  = gam[o_r0] * rsqrtf(var[o_r0] + EPS);
        float sh0 = beta[o_r0] - mean[o_r0] * s0;
        float bi0 = bias[o_r0];
        float s1  = gam[o_r1] * rsqrtf(var[o_r1] + EPS);
        float sh1 = beta[o_r1] - mean[o_r1] * s1;
        float bi1 = bias[o_r1];
        float* y0 = Y + (size_t)b * O * HW + (size_t)o_r0 * HW + p0;
        float* y1 = Y + (size_t)b * O * HW + (size_t)o_r1 * HW + p0;
        const float* rs0 = rsd ? rsd + (size_t)b * O * HW + (size_t)o_r0 * HW + p0 : nullptr;
        const float* rs1 = rsd ? rsd + (size_t)b * O * HW + (size_t)o_r1 * HW + p0 : nullptr;
#pragma unroll
        for (int nt = 0; nt < 16; nt++) {
            int p = nt * 8 + 2 * tig;
            float v00 = fmaxf((cc[nt][0] + bi0) * s0 + sh0, 0.f);
            float v01 = fmaxf((cc[nt][1] + bi0) * s0 + sh0, 0.f);
            float v10 = fmaxf((cc[nt][2] + bi1) * s1 + sh1, 0.f);
            float v11 = fmaxf((cc[nt][3] + bi1) * s1 + sh1, 0.f);
            if (rs0) {
                float2 r0v = *(const float2*)(rs0 + p);
                float2 r1v = *(const float2*)(rs1 + p);
                v00 += r0v.x; v01 += r0v.y; v10 += r1v.x; v11 += r1v.y;
            }
            *(float2*)(y0 + p) = make_float2(v00, v01);
            *(float2*)(y1 + p) = make_float2(v10, v11);
        }
    }
}

// ---------------- attention: R16 + gemm2 2-product (drop Plo·Vh) ----------------
#define B1PITCH 136
#define B2PITCH 72
#define B1ELEMS (64 * B1PITCH)
#define B2ELEMS (128 * B2PITCH)
#define STG_ELEMS (2 * B1ELEMS + 2 * B2ELEMS)
#define ATTN_SMEM (3 * STG_ELEMS * 2)

__global__ __launch_bounds__(256) void attn_mma_kernel(
    const float* __restrict__ x1,
    const __nv_bfloat16* __restrict__ x2h, const __nv_bfloat16* __restrict__ x2l,
    const __nv_bfloat16* __restrict__ x3h, const __nv_bfloat16* __restrict__ x3l,
    float* __restrict__ out)
{
    extern __shared__ __nv_bfloat16 smb[];

    const int tid  = threadIdx.x;
    const int w    = tid >> 5;
    const int lane = tid & 31;
    const int grp  = lane >> 2;
    const int tig  = lane & 3;
    const int b    = blockIdx.y;
    const int i0   = blockIdx.x * 128;
    const int r0   = w * 16 + grp;
    const int rowoff = (((lane >> 3) >> 1) << 3) + (lane & 7);
    const int khalf  = ((lane >> 3) & 1) << 3;

    uint32_t ahi[8][4], alo[8][4];
    {
        const float* a0p = x1 + (size_t)b * 524288 + (size_t)(i0 + r0) * 128;
        const float* a1p = a0p + 8 * 128;
#pragma unroll
        for (int kt = 0; kt < 8; kt++) {
            float2 e00 = *(const float2*)(a0p + kt * 16 + 2 * tig);
            float2 e01 = *(const float2*)(a0p + kt * 16 + 2 * tig + 8);
            float2 e10 = *(const float2*)(a1p + kt * 16 + 2 * tig);
            float2 e11 = *(const float2*)(a1p + kt * 16 + 2 * tig + 8);
            split2(e00.x, e00.y, ahi[kt][0], alo[kt][0]);
            split2(e10.x, e10.y, ahi[kt][1], alo[kt][1]);
            split2(e01.x, e01.y, ahi[kt][2], alo[kt][2]);
            split2(e11.x, e11.y, ahi[kt][3], alo[kt][3]);
        }
    }

    const __nv_bfloat16* X2Hb = x2h + (size_t)b * 131072;
    const __nv_bfloat16* X2Lb = x2l + (size_t)b * 131072;
    const __nv_bfloat16* X3Hb = x3h + (size_t)b * 131072;
    const __nv_bfloat16* X3Lb = x3l + (size_t)b * 131072;

    const uint32_t smbase = smem_u32(smb);

    auto stage = [&](int ch) {
        const int st = ch % 3;
        const uint32_t s0  = smbase + (uint32_t)st * (STG_ELEMS * 2);
        const uint32_t b1h = s0;
        const uint32_t b1l = s0 + B1ELEMS * 2;
        const uint32_t b2h = s0 + 2 * B1ELEMS * 2;
        const uint32_t b2l = b2h + B2ELEMS * 2;
        const int j0 = ch * 64;
#pragma unroll
        for (int l = 0; l < 4; l++) {
            int n = tid + l * 256;
            {
                int r = n >> 4, p = n & 15;
                uint32_t off = (uint32_t)(r * (B1PITCH * 2) + p * 16);
                CP_ASYNC16(b1h + off, X2Hb + (size_t)(j0 + r) * 128 + p * 8);
                CP_ASYNC16(b1l + off, X2Lb + (size_t)(j0 + r) * 128 + p * 8);
            }
            {
                int r = n >> 3, p = n & 7;
                uint32_t off = (uint32_t)(r * (B2PITCH * 2) + p * 16);
                CP_ASYNC16(b2h + off, X3Hb + (size_t)r * 1024 + j0 + p * 8);
                CP_ASYNC16(b2l + off, X3Lb + (size_t)r * 1024 + j0 + p * 8);
            }
        }
    };

    float o[16][4];
#pragma unroll
    for (int nt = 0; nt < 16; nt++)
#pragma unroll
        for (int q = 0; q < 4; q++) o[nt][q] = 0.f;
    float m0 = -CUDART_INF_F, m1 = -CUDART_INF_F, l0 = 0.f, l1 = 0.f;

    stage(0); CP_COMMIT();
    stage(1); CP_COMMIT();

    for (int ch = 0; ch < 16; ch++) {
        CP_WAIT1();
        __syncthreads();

        const uint32_t sbase = smbase + (uint32_t)(ch % 3) * (STG_ELEMS * 2);
        const uint32_t aB1H = sbase;
        const uint32_t aB1L = sbase + B1ELEMS * 2;
        const uint32_t aB2H = sbase + 2 * B1ELEMS * 2;
        const uint32_t aB2L = aB2H + B2ELEMS * 2;

        // ---- gemm1: 3-product (full accuracy into softmax) ----
        float s[8][4];
#pragma unroll
        for (int nt = 0; nt < 8; nt++)
#pragma unroll
            for (int q = 0; q < 4; q++) s[nt][q] = 0.f;

#pragma unroll
        for (int kt = 0; kt < 8; kt++) {
#pragma unroll
            for (int np = 0; np < 4; np++) {
                uint32_t off = (uint32_t)(((np * 16 + rowoff) * B1PITCH + kt * 16 + khalf) * 2);
                uint32_t h0, h1, h2, h3, q0, q1, q2, q3;
                ldsm4(h0, h1, h2, h3, aB1H + off);
                ldsm4(q0, q1, q2, q3, aB1L + off);
                int n0 = 2 * np, n1 = 2 * np + 1;
                mma_bf16(s[n0][0], s[n0][1], s[n0][2], s[n0][3],
                         ahi[kt][0], ahi[kt][1], ahi[kt][2], ahi[kt][3], h0, h1);
                mma_bf16(s[n0][0], s[n0][1], s[n0][2], s[n0][3],
                         ahi[kt][0], ahi[kt][1], ahi[kt][2], ahi[kt][3], q0, q1);
                mma_bf16(s[n0][0], s[n0][1], s[n0][2], s[n0][3],
                         alo[kt][0], alo[kt][1], alo[kt][2], alo[kt][3], h0, h1);
                mma_bf16(s[n1][0], s[n1][1], s[n1][2], s[n1][3],
                         ahi[kt][0], ahi[kt][1], ahi[kt][2], ahi[kt][3], h2, h3);
                mma_bf16(s[n1][0], s[n1][1], s[n1][2], s[n1][3],
                         ahi[kt][0], ahi[kt][1], ahi[kt][2], ahi[kt][3], q2, q3);
                mma_bf16(s[n1][0], s[n1][1], s[n1][2], s[n1][3],
                         alo[kt][0], alo[kt][1], alo[kt][2], alo[kt][3], h2, h3);
            }
        }

        // ---- online softmax ----
        float mx0 = s[0][0], mx1 = s[0][2];
#pragma unroll
        for (int nt = 0; nt < 8; nt++) {
            mx0 = fmaxf(mx0, fmaxf(s[nt][0], s[nt][1]));
            mx1 = fmaxf(mx1, fmaxf(s[nt][2], s[nt][3]));
        }
        mx0 = fmaxf(mx0, __shfl_xor_sync(0xffffffffu, mx0, 1));
        mx0 = fmaxf(mx0, __shfl_xor_sync(0xffffffffu, mx0, 2));
        mx1 = fmaxf(mx1, __shfl_xor_sync(0xffffffffu, mx1, 1));
        mx1 = fmaxf(mx1, __shfl_xor_sync(0xffffffffu, mx1, 2));
        float n0 = fmaxf(m0, mx0), n1 = fmaxf(m1, mx1);
        float f0 = __expf(m0 - n0), f1 = __expf(m1 - n1);
        m0 = n0; m1 = n1;
        float ps0 = 0.f, ps1 = 0.f;
#pragma unroll
        for (int nt = 0; nt < 8; nt++) {
            s[nt][0] = __expf(s[nt][0] - n0);
            s[nt][1] = __expf(s[nt][1] - n0);
            s[nt][2] = __expf(s[nt][2] - n1);
            s[nt][3] = __expf(s[nt][3] - n1);
            ps0 += s[nt][0] + s[nt][1];
            ps1 += s[nt][2] + s[nt][3];
        }
        ps0 += __shfl_xor_sync(0xffffffffu, ps0, 1);
        ps0 += __shfl_xor_sync(0xffffffffu, ps0, 2);
        ps1 += __shfl_xor_sync(0xffffffffu, ps1, 1);
        ps1 += __shfl_xor_sync(0xffffffffu, ps1, 2);
        l0 = l0 * f0 + ps0;
        l1 = l1 * f1 + ps1;
#pragma unroll
        for (int nt = 0; nt < 16; nt++) {
            o[nt][0] *= f0; o[nt][1] *= f0;
            o[nt][2] *= f1; o[nt][3] *= f1;
        }

        // ---- pack P (hi only; residual dropped — see round theory) ----
        uint32_t phi[4][4];
#pragma unroll
        for (int kt = 0; kt < 4; kt++) {
            phi[kt][0] = pack_bf16x2(s[2 * kt][0],     s[2 * kt][1]);
            phi[kt][1] = pack_bf16x2(s[2 * kt][2],     s[2 * kt][3]);
            phi[kt][2] = pack_bf16x2(s[2 * kt + 1][0], s[2 * kt + 1][1]);
            phi[kt][3] = pack_bf16x2(s[2 * kt + 1][2], s[2 * kt + 1][3]);
        }

        // ---- gemm2: O += Phi·Vh + Phi·Vl (2-product) ----
#pragma unroll
        for (int kt = 0; kt < 4; kt++) {
#pragma unroll
            for (int np = 0; np < 8; np++) {
                uint32_t off = (uint32_t)(((np * 16 + rowoff) * B2PITCH + kt * 16 + khalf) * 2);
                uint32_t h0, h1, h2, h3, q0, q1, q2, q3;
                ldsm4(h0, h1, h2, h3, aB2H + off);
                ldsm4(q0, q1, q2, q3, aB2L + off);
                int n0 = 2 * np, n1 = 2 * np + 1;
                mma_bf16(o[n0][0], o[n0][1], o[n0][2], o[n0][3],
                         phi[kt][0], phi[kt][1], phi[kt][2], phi[kt][3], h0, h1);
                mma_bf16(o[n0][0], o[n0][1], o[n0][2], o[n0][3],
                         phi[kt][0], phi[kt][1], phi[kt][2], phi[kt][3], q0, q1);
                mma_bf16(o[n1][0], o[n1][1], o[n1][2], o[n1][3],
                         phi[kt][0], phi[kt][1], phi[kt][2], phi[kt][3], h2, h3);
                mma_bf16(o[n1][0], o[n1][1], o[n1][2], o[n1][3],
                         phi[kt][0], phi[kt][1], phi[kt][2], phi[kt][3], q2, q3);
            }
        }

        if (ch + 2 < 16) stage(ch + 2);
        CP_COMMIT();
    }

    float inv0 = 1.0f / l0, inv1 = 1.0f / l1;
    float* og0 = out + (size_t)b * 524288 + (size_t)(i0 + r0) * 128;
    float* og1 = og0 + 8 * 128;
#pragma unroll
    for (int nt = 0; nt < 16; nt++) {
        *(float2*)(og0 + nt * 8 + 2 * tig) = make_float2(o[nt][0] * inv0, o[nt][1] * inv0);
        *(float2*)(og1 + nt * 8 + 2 * tig) = make_float2(o[nt][2] * inv1, o[nt][3] * inv1);
    }
}

// ---------------- launcher ----------------
extern "C" void kernel_launch(void* const* d_in, const int* in_sizes, int n_in,
                              void* d_out, int out_size)
{
    const float* a       = (const float*)d_in[0];
    const float* conv1_w = (const float*)d_in[1];
    const float* conv1_b = (const float*)d_in[2];
    const float* bn1_g   = (const float*)d_in[3];
    const float* bn1_b   = (const float*)d_in[4];
    const float* bn1_m   = (const float*)d_in[5];
    const float* bn1_v   = (const float*)d_in[6];
    const float* conv2_w = (const float*)d_in[7];
    const float* conv2_b = (const float*)d_in[8];
    const float* bn2_g   = (const float*)d_in[9];
    const float* bn2_b   = (const float*)d_in[10];
    const float* bn2_m   = (const float*)d_in[11];
    const float* bn2_v   = (const float*)d_in[12];
    const float* conv3_w = (const float*)d_in[13];
    const float* conv3_b = (const float*)d_in[14];
    const float* bn3_g   = (const float*)d_in[15];
    const float* bn3_b   = (const float*)d_in[16];
    const float* bn3_m   = (const float*)d_in[17];
    const float* bn3_v   = (const float*)d_in[18];
    float* out = (float*)d_out;

    float *p_x1, *p_y2, *p_attn;
    __nv_bfloat16 *p_x2h, *p_x2l, *p_x3h, *p_x3l, *p_ath, *p_atl;
    cudaGetSymbolAddress((void**)&p_x1,   g_x1);
    cudaGetSymbolAddress((void**)&p_y2,   g_y2);
    cudaGetSymbolAddress((void**)&p_attn, g_attn);
    cudaGetSymbolAddress((void**)&p_x2h,  g_x2t_hi);
    cudaGetSymbolAddress((void**)&p_x2l,  g_x2t_lo);
    cudaGetSymbolAddress((void**)&p_x3h,  g_x3t_hi);
    cudaGetSymbolAddress((void**)&p_x3l,  g_x3t_lo);
    cudaGetSymbolAddress((void**)&p_ath,  g_at_hi);
    cudaGetSymbolAddress((void**)&p_atl,  g_at_lo);

    cudaFuncSetAttribute(attn_mma_kernel,  cudaFuncAttributeMaxDynamicSharedMemorySize, ATTN_SMEM);
    cudaFuncSetAttribute(conv_dual_kernel, cudaFuncAttributeMaxDynamicSharedMemorySize, CDUAL_SMEM);

    dim3 blk(256);

    transpose_split_kernel<<<dim3(128, 8, 8), dim3(32, 8)>>>(a, p_ath, p_atl, 256, 4096);

    conv_dual_kernel<<<dim3(32, 1, 8), blk, CDUAL_SMEM>>>(
        p_ath, p_atl,
        conv1_w, conv1_b, bn1_g, bn1_b, bn1_m, bn1_v, p_x1, nullptr,
        conv2_w, conv2_b, bn2_g, bn2_b, bn2_m, bn2_v, p_y2, nullptr,
        256, 128);

    pool_split_kernel<<<dim3(32, 4, 8), blk>>>(p_y2, p_x2h, p_x2l, p_x3h, p_x3l);

    attn_mma_kernel<<<dim3(32, 8), blk, ATTN_SMEM>>>(
        p_x1, p_x2h, p_x2l, p_x3h, p_x3l, p_attn);

    transpose_split_kernel<<<dim3(128, 4, 8), dim3(32, 8)>>>(p_attn, p_ath, p_atl, 128, 4096);

    conv_dual_kernel<<<dim3(32, 1, 8), blk, CDUAL_SMEM>>>(
        p_ath, p_atl,
        conv3_w,             conv3_b,       bn3_g,       bn3_b,       bn3_m,       bn3_v,
        out,                 a,
        conv3_w + 128 * 128, conv3_b + 128, bn3_g + 128, bn3_b + 128, bn3_m + 128, bn3_v + 128,
        out + 128 * 4096,    a + 128 * 4096,
        128, 256);
}